// round 1
// baseline (speedup 1.0000x reference)
#include <cuda_runtime.h>
#include <math.h>

#define BB 4
#define TT 2048
#define CC 1024
#define HH 16
#define DH 64
#define MROWS (BB*TT)
#define C3   (3*CC)

// scratch (no cudaMalloc allowed)
__device__ float g_qkv[(size_t)MROWS * C3];   // [M, 3C]  q|k|v per row
__device__ float g_y[(size_t)MROWS * CC];     // [M, C]   attention output

// ---------------------------------------------------------------------------
// SGEMM: C[M,N] = A[M,K] @ B[K,N] + bias[N]
// block 256 threads, tile 128x128, K-tile 16, 8x8 per thread
// ---------------------------------------------------------------------------
__global__ __launch_bounds__(256) void sgemm_bias(
    const float* __restrict__ A, const float* __restrict__ Bm,
    const float* __restrict__ bias, float* __restrict__ Cm,
    int Mn, int Nn, int Kn)
{
    __shared__ float As[16][128];   // transposed A tile
    __shared__ float Bs[16][128];

    const int tid = threadIdx.x;
    const int tr  = tid >> 4;       // 0..15
    const int tc  = tid & 15;       // 0..15
    const int row0 = blockIdx.y * 128;
    const int col0 = blockIdx.x * 128;

    float acc[8][8] = {};

    for (int k0 = 0; k0 < Kn; k0 += 16) {
        // load A 128x16 (transposed into As[k][row])
        #pragma unroll
        for (int i = 0; i < 2; i++) {
            int f  = tid + i * 256;          // 0..511 float4 slots
            int r  = f >> 2;                 // 0..127
            int kq = (f & 3) << 2;           // 0,4,8,12
            float4 v = *reinterpret_cast<const float4*>(
                &A[(size_t)(row0 + r) * Kn + k0 + kq]);
            As[kq + 0][r] = v.x; As[kq + 1][r] = v.y;
            As[kq + 2][r] = v.z; As[kq + 3][r] = v.w;
        }
        // load B 16x128
        #pragma unroll
        for (int i = 0; i < 2; i++) {
            int f  = tid + i * 256;
            int r  = f >> 5;                 // 0..15
            int c4 = (f & 31) << 2;          // 0..124
            *reinterpret_cast<float4*>(&Bs[r][c4]) =
                *reinterpret_cast<const float4*>(
                    &Bm[(size_t)(k0 + r) * Nn + col0 + c4]);
        }
        __syncthreads();

        #pragma unroll
        for (int kk = 0; kk < 16; kk++) {
            float a[8], b[8];
            *reinterpret_cast<float4*>(a)     = *reinterpret_cast<float4*>(&As[kk][tr * 8]);
            *reinterpret_cast<float4*>(a + 4) = *reinterpret_cast<float4*>(&As[kk][tr * 8 + 4]);
            *reinterpret_cast<float4*>(b)     = *reinterpret_cast<float4*>(&Bs[kk][tc * 8]);
            *reinterpret_cast<float4*>(b + 4) = *reinterpret_cast<float4*>(&Bs[kk][tc * 8 + 4]);
            #pragma unroll
            for (int i = 0; i < 8; i++)
                #pragma unroll
                for (int j = 0; j < 8; j++)
                    acc[i][j] = fmaf(a[i], b[j], acc[i][j]);
        }
        __syncthreads();
    }

    #pragma unroll
    for (int i = 0; i < 8; i++) {
        int r = row0 + tr * 8 + i;
        #pragma unroll
        for (int j = 0; j < 8; j += 4) {
            int c = col0 + tc * 8 + j;
            float4 v;
            v.x = acc[i][j + 0] + __ldg(&bias[c + 0]);
            v.y = acc[i][j + 1] + __ldg(&bias[c + 1]);
            v.z = acc[i][j + 2] + __ldg(&bias[c + 2]);
            v.w = acc[i][j + 3] + __ldg(&bias[c + 3]);
            *reinterpret_cast<float4*>(&Cm[(size_t)r * Nn + c]) = v;
        }
    }
}

// ---------------------------------------------------------------------------
// Flash attention (causal), fp32. Br=Bc=64, D=64.
// grid: (T/64, H, B), block 256 (16x16), online softmax in registers.
// smem: Qs[64][68], KVs[64][68] (K then V), Ss[64][64]  -> 50 KB dynamic
// ---------------------------------------------------------------------------
#define QPAD 68
#define SM_Q   0
#define SM_KV  (64 * QPAD)
#define SM_S   (2 * 64 * QPAD)
#define SMEM_FLOATS (2 * 64 * QPAD + 64 * 64)

__global__ __launch_bounds__(256) void flash_attn(
    const float* __restrict__ qkv, float* __restrict__ y)
{
    extern __shared__ float sm[];
    float* Qs  = sm + SM_Q;
    float* KVs = sm + SM_KV;
    float* Ss  = sm + SM_S;

    const int tid = threadIdx.x;
    const int ty  = tid >> 4;   // 0..15 -> rows ty*4..ty*4+3
    const int tx  = tid & 15;   // 0..15 -> cols tx*4..tx*4+3
    const int qt  = blockIdx.x;
    const int h   = blockIdx.y;
    const int b   = blockIdx.z;
    const int q0  = qt * 64;
    const float scale = 0.125f;  // 1/sqrt(64)

    // load Q tile [64 x 64]
    const size_t baseQ = (size_t)(b * TT + q0) * C3 + h * DH;
    #pragma unroll
    for (int i = 0; i < 4; i++) {
        int f  = tid + i * 256;       // 0..1023 float4 slots
        int r  = f >> 4;              // 0..63
        int d4 = (f & 15) << 2;       // 0..60
        float4 v = *reinterpret_cast<const float4*>(&qkv[baseQ + (size_t)r * C3 + d4]);
        Qs[r * QPAD + d4 + 0] = v.x; Qs[r * QPAD + d4 + 1] = v.y;
        Qs[r * QPAD + d4 + 2] = v.z; Qs[r * QPAD + d4 + 3] = v.w;
    }

    float m_i[4], l_i[4], o[4][4];
    #pragma unroll
    for (int i = 0; i < 4; i++) {
        m_i[i] = -1e30f; l_i[i] = 0.0f;
        #pragma unroll
        for (int j = 0; j < 4; j++) o[i][j] = 0.0f;
    }

    for (int kt = 0; kt <= qt; kt++) {
        const int k0 = kt * 64;
        // load K tile
        const size_t baseK = (size_t)(b * TT + k0) * C3 + CC + h * DH;
        __syncthreads();   // protect KVs/Ss from previous iteration
        #pragma unroll
        for (int i = 0; i < 4; i++) {
            int f  = tid + i * 256;
            int r  = f >> 4;
            int d4 = (f & 15) << 2;
            float4 v = *reinterpret_cast<const float4*>(&qkv[baseK + (size_t)r * C3 + d4]);
            KVs[r * QPAD + d4 + 0] = v.x; KVs[r * QPAD + d4 + 1] = v.y;
            KVs[r * QPAD + d4 + 2] = v.z; KVs[r * QPAD + d4 + 3] = v.w;
        }
        __syncthreads();

        // S = Q @ K^T (4x4 per thread)
        float s[4][4] = {};
        #pragma unroll
        for (int d = 0; d < 64; d += 4) {
            float4 qv[4], kv[4];
            #pragma unroll
            for (int i = 0; i < 4; i++)
                qv[i] = *reinterpret_cast<float4*>(&Qs[(ty * 4 + i) * QPAD + d]);
            #pragma unroll
            for (int j = 0; j < 4; j++)
                kv[j] = *reinterpret_cast<float4*>(&KVs[(tx * 4 + j) * QPAD + d]);
            #pragma unroll
            for (int i = 0; i < 4; i++)
                #pragma unroll
                for (int j = 0; j < 4; j++) {
                    s[i][j] = fmaf(qv[i].x, kv[j].x, s[i][j]);
                    s[i][j] = fmaf(qv[i].y, kv[j].y, s[i][j]);
                    s[i][j] = fmaf(qv[i].z, kv[j].z, s[i][j]);
                    s[i][j] = fmaf(qv[i].w, kv[j].w, s[i][j]);
                }
        }
        // scale + causal mask (only diagonal tile needs masking)
        #pragma unroll
        for (int i = 0; i < 4; i++)
            #pragma unroll
            for (int j = 0; j < 4; j++) {
                s[i][j] *= scale;
                if (kt == qt && (tx * 4 + j) > (ty * 4 + i)) s[i][j] = -1e30f;
            }

        // online softmax: row reductions across the 16 tx lanes (half-warp)
        #pragma unroll
        for (int i = 0; i < 4; i++) {
            float mt = fmaxf(fmaxf(s[i][0], s[i][1]), fmaxf(s[i][2], s[i][3]));
            #pragma unroll
            for (int k = 1; k < 16; k <<= 1)
                mt = fmaxf(mt, __shfl_xor_sync(0xffffffffu, mt, k));
            float mnew = fmaxf(m_i[i], mt);
            float corr = __expf(m_i[i] - mnew);
            float rs = 0.0f;
            #pragma unroll
            for (int j = 0; j < 4; j++) {
                float p = __expf(s[i][j] - mnew);
                Ss[(ty * 4 + i) * 64 + tx * 4 + j] = p;
                rs += p;
            }
            #pragma unroll
            for (int k = 1; k < 16; k <<= 1)
                rs += __shfl_xor_sync(0xffffffffu, rs, k);
            l_i[i] = l_i[i] * corr + rs;
            m_i[i] = mnew;
            #pragma unroll
            for (int j = 0; j < 4; j++) o[i][j] *= corr;
        }
        __syncthreads();   // S reads of K done, Ss written

        // load V tile into KVs
        const size_t baseV = (size_t)(b * TT + k0) * C3 + 2 * CC + h * DH;
        #pragma unroll
        for (int i = 0; i < 4; i++) {
            int f  = tid + i * 256;
            int r  = f >> 4;
            int d4 = (f & 15) << 2;
            float4 v = *reinterpret_cast<const float4*>(&qkv[baseV + (size_t)r * C3 + d4]);
            KVs[r * QPAD + d4 + 0] = v.x; KVs[r * QPAD + d4 + 1] = v.y;
            KVs[r * QPAD + d4 + 2] = v.z; KVs[r * QPAD + d4 + 3] = v.w;
        }
        __syncthreads();

        // O += P @ V
        #pragma unroll
        for (int k = 0; k < 64; k += 4) {
            float4 p4[4], v4[4];
            #pragma unroll
            for (int i = 0; i < 4; i++)
                p4[i] = *reinterpret_cast<float4*>(&Ss[(ty * 4 + i) * 64 + k]);
            #pragma unroll
            for (int kk = 0; kk < 4; kk++)
                v4[kk] = *reinterpret_cast<float4*>(&KVs[(k + kk) * QPAD + tx * 4]);
            #pragma unroll
            for (int i = 0; i < 4; i++) {
                o[i][0] = fmaf(p4[i].x, v4[0].x, o[i][0]);
                o[i][1] = fmaf(p4[i].x, v4[0].y, o[i][1]);
                o[i][2] = fmaf(p4[i].x, v4[0].z, o[i][2]);
                o[i][3] = fmaf(p4[i].x, v4[0].w, o[i][3]);
                o[i][0] = fmaf(p4[i].y, v4[1].x, o[i][0]);
                o[i][1] = fmaf(p4[i].y, v4[1].y, o[i][1]);
                o[i][2] = fmaf(p4[i].y, v4[1].z, o[i][2]);
                o[i][3] = fmaf(p4[i].y, v4[1].w, o[i][3]);
                o[i][0] = fmaf(p4[i].z, v4[2].x, o[i][0]);
                o[i][1] = fmaf(p4[i].z, v4[2].y, o[i][1]);
                o[i][2] = fmaf(p4[i].z, v4[2].z, o[i][2]);
                o[i][3] = fmaf(p4[i].z, v4[2].w, o[i][3]);
                o[i][0] = fmaf(p4[i].w, v4[3].x, o[i][0]);
                o[i][1] = fmaf(p4[i].w, v4[3].y, o[i][1]);
                o[i][2] = fmaf(p4[i].w, v4[3].z, o[i][2]);
                o[i][3] = fmaf(p4[i].w, v4[3].w, o[i][3]);
            }
        }
    }

    // write y[b, q, h*64 + d]
    #pragma unroll
    for (int i = 0; i < 4; i++) {
        int r = q0 + ty * 4 + i;
        float inv = 1.0f / l_i[i];
        float4 v;
        v.x = o[i][0] * inv; v.y = o[i][1] * inv;
        v.z = o[i][2] * inv; v.w = o[i][3] * inv;
        *reinterpret_cast<float4*>(
            &g_y[(size_t)(b * TT + r) * CC + h * DH + tx * 4]) = v;
    }
}

// ---------------------------------------------------------------------------
extern "C" void kernel_launch(void* const* d_in, const int* in_sizes, int n_in,
                              void* d_out, int out_size)
{
    const float* x      = (const float*)d_in[0];
    const float* W_attn = (const float*)d_in[1];
    const float* b_attn = (const float*)d_in[2];
    const float* W_proj = (const float*)d_in[3];
    const float* b_proj = (const float*)d_in[4];
    float* out = (float*)d_out;

    float *qkv_ptr, *y_ptr;
    cudaGetSymbolAddress((void**)&qkv_ptr, g_qkv);
    cudaGetSymbolAddress((void**)&y_ptr, g_y);

    static bool attr_set = false;
    if (!attr_set) {
        cudaFuncSetAttribute(flash_attn,
                             cudaFuncAttributeMaxDynamicSharedMemorySize,
                             SMEM_FLOATS * sizeof(float));
        attr_set = true;
    }

    // 1) qkv = x @ W_attn + b_attn
    sgemm_bias<<<dim3(C3 / 128, MROWS / 128), 256>>>(
        x, W_attn, b_attn, qkv_ptr, MROWS, C3, CC);

    // 2) causal flash attention -> g_y
    flash_attn<<<dim3(TT / 64, HH, BB), 256, SMEM_FLOATS * sizeof(float)>>>(
        qkv_ptr, y_ptr);

    // 3) out = y @ W_proj + b_proj
    sgemm_bias<<<dim3(CC / 128, MROWS / 128), 256>>>(
        y_ptr, W_proj, b_proj, out, MROWS, CC, CC);
}

// round 3
// speedup vs baseline: 1.4598x; 1.4598x over previous
#include <cuda_runtime.h>
#include <math.h>
#include <stdint.h>

#define BB 4
#define TT 2048
#define CC 1024
#define HH 16
#define DH 64
#define MROWS (BB*TT)
#define C3   (3*CC)

// scratch (no cudaMalloc allowed)
__device__ float g_qkv[(size_t)MROWS * C3];   // [M, 3C]  q|k|v per row
__device__ float g_y[(size_t)MROWS * CC];     // [M, C]   attention output

// ---------------------------------------------------------------------------
// TF32 tensor-core SGEMM: C[M,N] = A[M,K] @ B[K,N] + bias[N]
// block 256 threads (8 warps, 2x4), tile 128x128, BK=32, warp tile 64x32
// mma.sync.aligned.m16n8k8.row.col.f32.tf32.tf32.f32
// ---------------------------------------------------------------------------
#define ASTRIDE 36    // floats per A row in smem (128x36)   -> conflict-free frags
#define BSTRIDE 136   // floats per B row in smem (32x136)   -> conflict-free frags

__device__ __forceinline__ uint32_t f2tf32(float x) {
    uint32_t r;
    asm("cvt.rna.tf32.f32 %0, %1;" : "=r"(r) : "f"(x));
    return r;
}

__global__ __launch_bounds__(256, 2) void sgemm_tf32(
    const float* __restrict__ A, const float* __restrict__ Bm,
    const float* __restrict__ bias, float* __restrict__ Cm,
    int Mn, int Nn, int Kn)
{
    __shared__ float As[128 * ASTRIDE];
    __shared__ float Bs[32 * BSTRIDE];

    const int tid  = threadIdx.x;
    const int lane = tid & 31;
    const int warp = tid >> 5;
    const int wr   = warp & 1;    // warp row (2)
    const int wc   = warp >> 1;   // warp col (4)
    const int row0 = blockIdx.y * 128;
    const int col0 = blockIdx.x * 128;

    const int lr = lane >> 2;   // 0..7
    const int lc = lane & 3;    // 0..3

    float acc[4][4][4];
    #pragma unroll
    for (int i = 0; i < 4; i++)
        #pragma unroll
        for (int j = 0; j < 4; j++)
            #pragma unroll
            for (int k = 0; k < 4; k++) acc[i][j][k] = 0.0f;

    for (int k0 = 0; k0 < Kn; k0 += 32) {
        // ---- load A 128x32 (row-major into As[m][k], tf32-rounded) ----
        #pragma unroll
        for (int i = 0; i < 4; i++) {
            int f  = tid + i * 256;          // 0..1023 float4 slots
            int r  = f >> 3;                 // 0..127
            int c4 = (f & 7) << 2;           // 0..28
            float4 v = *reinterpret_cast<const float4*>(
                &A[(size_t)(row0 + r) * Kn + k0 + c4]);
            float4 w;
            w.x = __uint_as_float(f2tf32(v.x));
            w.y = __uint_as_float(f2tf32(v.y));
            w.z = __uint_as_float(f2tf32(v.z));
            w.w = __uint_as_float(f2tf32(v.w));
            *reinterpret_cast<float4*>(&As[r * ASTRIDE + c4]) = w;
        }
        // ---- load B 32x128 (into Bs[k][n], tf32-rounded) ----
        #pragma unroll
        for (int i = 0; i < 4; i++) {
            int f  = tid + i * 256;
            int kr = f >> 5;                 // 0..31
            int n4 = (f & 31) << 2;          // 0..124
            float4 v = *reinterpret_cast<const float4*>(
                &Bm[(size_t)(k0 + kr) * Nn + col0 + n4]);
            float4 w;
            w.x = __uint_as_float(f2tf32(v.x));
            w.y = __uint_as_float(f2tf32(v.y));
            w.z = __uint_as_float(f2tf32(v.z));
            w.w = __uint_as_float(f2tf32(v.w));
            *reinterpret_cast<float4*>(&Bs[kr * BSTRIDE + n4]) = w;
        }
        __syncthreads();

        #pragma unroll
        for (int ks = 0; ks < 4; ks++) {
            const int kk = ks * 8;
            uint32_t a[4][4], b[4][2];
            #pragma unroll
            for (int mt = 0; mt < 4; mt++) {
                int m = wr * 64 + mt * 16 + lr;
                int k = kk + lc;
                a[mt][0] = __float_as_uint(As[m * ASTRIDE + k]);
                a[mt][1] = __float_as_uint(As[(m + 8) * ASTRIDE + k]);
                a[mt][2] = __float_as_uint(As[m * ASTRIDE + k + 4]);
                a[mt][3] = __float_as_uint(As[(m + 8) * ASTRIDE + k + 4]);
            }
            #pragma unroll
            for (int nt = 0; nt < 4; nt++) {
                int n = wc * 32 + nt * 8 + lr;
                int k = kk + lc;
                b[nt][0] = __float_as_uint(Bs[k * BSTRIDE + n]);
                b[nt][1] = __float_as_uint(Bs[(k + 4) * BSTRIDE + n]);
            }
            #pragma unroll
            for (int mt = 0; mt < 4; mt++)
                #pragma unroll
                for (int nt = 0; nt < 4; nt++)
                    asm volatile(
                        "mma.sync.aligned.m16n8k8.row.col.f32.tf32.tf32.f32 "
                        "{%0,%1,%2,%3}, {%4,%5,%6,%7}, {%8,%9}, {%0,%1,%2,%3};"
                        : "+f"(acc[mt][nt][0]), "+f"(acc[mt][nt][1]),
                          "+f"(acc[mt][nt][2]), "+f"(acc[mt][nt][3])
                        : "r"(a[mt][0]), "r"(a[mt][1]), "r"(a[mt][2]), "r"(a[mt][3]),
                          "r"(b[nt][0]), "r"(b[nt][1]));
        }
        __syncthreads();
    }

    // ---- epilogue: C frag rows = base + lr (+8), cols = base + 2*lc + {0,1} ----
    #pragma unroll
    for (int mt = 0; mt < 4; mt++) {
        int r = row0 + wr * 64 + mt * 16 + lr;
        #pragma unroll
        for (int nt = 0; nt < 4; nt++) {
            int c = col0 + wc * 32 + nt * 8 + 2 * lc;
            float b0 = __ldg(&bias[c]);
            float b1 = __ldg(&bias[c + 1]);
            float2 v0 = make_float2(acc[mt][nt][0] + b0, acc[mt][nt][1] + b1);
            float2 v1 = make_float2(acc[mt][nt][2] + b0, acc[mt][nt][3] + b1);
            *reinterpret_cast<float2*>(&Cm[(size_t)r * Nn + c]) = v0;
            *reinterpret_cast<float2*>(&Cm[(size_t)(r + 8) * Nn + c]) = v1;
        }
    }
}

// ---------------------------------------------------------------------------
// Flash attention (causal), fp32. Br=Bc=64, D=64.
// ---------------------------------------------------------------------------
#define QPAD 68
#define SM_Q   0
#define SM_KV  (64 * QPAD)
#define SM_S   (2 * 64 * QPAD)
#define SMEM_FLOATS (2 * 64 * QPAD + 64 * 64)

__global__ __launch_bounds__(256) void flash_attn(
    const float* __restrict__ qkv, float* __restrict__ y)
{
    extern __shared__ float sm[];
    float* Qs  = sm + SM_Q;
    float* KVs = sm + SM_KV;
    float* Ss  = sm + SM_S;

    const int tid = threadIdx.x;
    const int ty  = tid >> 4;
    const int tx  = tid & 15;
    const int qt  = blockIdx.x;
    const int h   = blockIdx.y;
    const int b   = blockIdx.z;
    const int q0  = qt * 64;
    const float scale = 0.125f;

    const size_t baseQ = (size_t)(b * TT + q0) * C3 + h * DH;
    #pragma unroll
    for (int i = 0; i < 4; i++) {
        int f  = tid + i * 256;
        int r  = f >> 4;
        int d4 = (f & 15) << 2;
        float4 v = *reinterpret_cast<const float4*>(&qkv[baseQ + (size_t)r * C3 + d4]);
        Qs[r * QPAD + d4 + 0] = v.x; Qs[r * QPAD + d4 + 1] = v.y;
        Qs[r * QPAD + d4 + 2] = v.z; Qs[r * QPAD + d4 + 3] = v.w;
    }

    float m_i[4], l_i[4], o[4][4];
    #pragma unroll
    for (int i = 0; i < 4; i++) {
        m_i[i] = -1e30f; l_i[i] = 0.0f;
        #pragma unroll
        for (int j = 0; j < 4; j++) o[i][j] = 0.0f;
    }

    for (int kt = 0; kt <= qt; kt++) {
        const int k0 = kt * 64;
        const size_t baseK = (size_t)(b * TT + k0) * C3 + CC + h * DH;
        __syncthreads();
        #pragma unroll
        for (int i = 0; i < 4; i++) {
            int f  = tid + i * 256;
            int r  = f >> 4;
            int d4 = (f & 15) << 2;
            float4 v = *reinterpret_cast<const float4*>(&qkv[baseK + (size_t)r * C3 + d4]);
            KVs[r * QPAD + d4 + 0] = v.x; KVs[r * QPAD + d4 + 1] = v.y;
            KVs[r * QPAD + d4 + 2] = v.z; KVs[r * QPAD + d4 + 3] = v.w;
        }
        __syncthreads();

        float s[4][4] = {};
        #pragma unroll
        for (int d = 0; d < 64; d += 4) {
            float4 qv[4], kv[4];
            #pragma unroll
            for (int i = 0; i < 4; i++)
                qv[i] = *reinterpret_cast<float4*>(&Qs[(ty * 4 + i) * QPAD + d]);
            #pragma unroll
            for (int j = 0; j < 4; j++)
                kv[j] = *reinterpret_cast<float4*>(&KVs[(tx * 4 + j) * QPAD + d]);
            #pragma unroll
            for (int i = 0; i < 4; i++)
                #pragma unroll
                for (int j = 0; j < 4; j++) {
                    s[i][j] = fmaf(qv[i].x, kv[j].x, s[i][j]);
                    s[i][j] = fmaf(qv[i].y, kv[j].y, s[i][j]);
                    s[i][j] = fmaf(qv[i].z, kv[j].z, s[i][j]);
                    s[i][j] = fmaf(qv[i].w, kv[j].w, s[i][j]);
                }
        }
        #pragma unroll
        for (int i = 0; i < 4; i++)
            #pragma unroll
            for (int j = 0; j < 4; j++) {
                s[i][j] *= scale;
                if (kt == qt && (tx * 4 + j) > (ty * 4 + i)) s[i][j] = -1e30f;
            }

        #pragma unroll
        for (int i = 0; i < 4; i++) {
            float mt = fmaxf(fmaxf(s[i][0], s[i][1]), fmaxf(s[i][2], s[i][3]));
            #pragma unroll
            for (int k = 1; k < 16; k <<= 1)
                mt = fmaxf(mt, __shfl_xor_sync(0xffffffffu, mt, k));
            float mnew = fmaxf(m_i[i], mt);
            float corr = __expf(m_i[i] - mnew);
            float rs = 0.0f;
            #pragma unroll
            for (int j = 0; j < 4; j++) {
                float p = __expf(s[i][j] - mnew);
                Ss[(ty * 4 + i) * 64 + tx * 4 + j] = p;
                rs += p;
            }
            #pragma unroll
            for (int k = 1; k < 16; k <<= 1)
                rs += __shfl_xor_sync(0xffffffffu, rs, k);
            l_i[i] = l_i[i] * corr + rs;
            m_i[i] = mnew;
            #pragma unroll
            for (int j = 0; j < 4; j++) o[i][j] *= corr;
        }
        __syncthreads();

        const size_t baseV = (size_t)(b * TT + k0) * C3 + 2 * CC + h * DH;
        #pragma unroll
        for (int i = 0; i < 4; i++) {
            int f  = tid + i * 256;
            int r  = f >> 4;
            int d4 = (f & 15) << 2;
            float4 v = *reinterpret_cast<const float4*>(&qkv[baseV + (size_t)r * C3 + d4]);
            KVs[r * QPAD + d4 + 0] = v.x; KVs[r * QPAD + d4 + 1] = v.y;
            KVs[r * QPAD + d4 + 2] = v.z; KVs[r * QPAD + d4 + 3] = v.w;
        }
        __syncthreads();

        #pragma unroll
        for (int k = 0; k < 64; k += 4) {
            float4 p4[4], v4[4];
            #pragma unroll
            for (int i = 0; i < 4; i++)
                p4[i] = *reinterpret_cast<float4*>(&Ss[(ty * 4 + i) * 64 + k]);
            #pragma unroll
            for (int kk = 0; kk < 4; kk++)
                v4[kk] = *reinterpret_cast<float4*>(&KVs[(k + kk) * QPAD + tx * 4]);
            #pragma unroll
            for (int i = 0; i < 4; i++) {
                o[i][0] = fmaf(p4[i].x, v4[0].x, o[i][0]);
                o[i][1] = fmaf(p4[i].x, v4[0].y, o[i][1]);
                o[i][2] = fmaf(p4[i].x, v4[0].z, o[i][2]);
                o[i][3] = fmaf(p4[i].x, v4[0].w, o[i][3]);
                o[i][0] = fmaf(p4[i].y, v4[1].x, o[i][0]);
                o[i][1] = fmaf(p4[i].y, v4[1].y, o[i][1]);
                o[i][2] = fmaf(p4[i].y, v4[1].z, o[i][2]);
                o[i][3] = fmaf(p4[i].y, v4[1].w, o[i][3]);
                o[i][0] = fmaf(p4[i].z, v4[2].x, o[i][0]);
                o[i][1] = fmaf(p4[i].z, v4[2].y, o[i][1]);
                o[i][2] = fmaf(p4[i].z, v4[2].z, o[i][2]);
                o[i][3] = fmaf(p4[i].z, v4[2].w, o[i][3]);
                o[i][0] = fmaf(p4[i].w, v4[3].x, o[i][0]);
                o[i][1] = fmaf(p4[i].w, v4[3].y, o[i][1]);
                o[i][2] = fmaf(p4[i].w, v4[3].z, o[i][2]);
                o[i][3] = fmaf(p4[i].w, v4[3].w, o[i][3]);
            }
        }
    }

    #pragma unroll
    for (int i = 0; i < 4; i++) {
        int r = q0 + ty * 4 + i;
        float inv = 1.0f / l_i[i];
        float4 v;
        v.x = o[i][0] * inv; v.y = o[i][1] * inv;
        v.z = o[i][2] * inv; v.w = o[i][3] * inv;
        *reinterpret_cast<float4*>(
            &g_y[(size_t)(b * TT + r) * CC + h * DH + tx * 4]) = v;
    }
}

// ---------------------------------------------------------------------------
extern "C" void kernel_launch(void* const* d_in, const int* in_sizes, int n_in,
                              void* d_out, int out_size)
{
    const float* x      = (const float*)d_in[0];
    const float* W_attn = (const float*)d_in[1];
    const float* b_attn = (const float*)d_in[2];
    const float* W_proj = (const float*)d_in[3];
    const float* b_proj = (const float*)d_in[4];
    float* out = (float*)d_out;

    float *qkv_ptr, *y_ptr;
    cudaGetSymbolAddress((void**)&qkv_ptr, g_qkv);
    cudaGetSymbolAddress((void**)&y_ptr, g_y);

    static bool attr_set = false;
    if (!attr_set) {
        cudaFuncSetAttribute(flash_attn,
                             cudaFuncAttributeMaxDynamicSharedMemorySize,
                             SMEM_FLOATS * sizeof(float));
        attr_set = true;
    }

    // 1) qkv = x @ W_attn + b_attn   (TF32 tensor cores)
    sgemm_tf32<<<dim3(C3 / 128, MROWS / 128), 256>>>(
        x, W_attn, b_attn, qkv_ptr, MROWS, C3, CC);

    // 2) causal flash attention -> g_y
    flash_attn<<<dim3(TT / 64, HH, BB), 256, SMEM_FLOATS * sizeof(float)>>>(
        qkv_ptr, y_ptr);

    // 3) out = y @ W_proj + b_proj   (TF32 tensor cores)
    sgemm_tf32<<<dim3(CC / 128, MROWS / 128), 256>>>(
        y_ptr, W_proj, b_proj, out, MROWS, CC, CC);
}

// round 4
// speedup vs baseline: 3.7029x; 2.5365x over previous
#include <cuda_runtime.h>
#include <math.h>
#include <stdint.h>

#define BB 4
#define TT 2048
#define CC 1024
#define HH 16
#define DH 64
#define MROWS (BB*TT)
#define C3   (3*CC)

__device__ float g_qkv[(size_t)MROWS * C3];   // [M, 3C]
__device__ float g_y[(size_t)MROWS * CC];     // [M, C]

__device__ __forceinline__ uint32_t f2tf32(float x) {
    uint32_t r;
    asm("cvt.rna.tf32.f32 %0, %1;" : "=r"(r) : "f"(x));
    return r;
}

// ---------------------------------------------------------------------------
// TF32 tensor-core SGEMM (unchanged from R3)
// ---------------------------------------------------------------------------
#define ASTRIDE 36
#define BSTRIDE 136

__global__ __launch_bounds__(256, 2) void sgemm_tf32(
    const float* __restrict__ A, const float* __restrict__ Bm,
    const float* __restrict__ bias, float* __restrict__ Cm,
    int Mn, int Nn, int Kn)
{
    __shared__ float As[128 * ASTRIDE];
    __shared__ float Bs[32 * BSTRIDE];

    const int tid  = threadIdx.x;
    const int lane = tid & 31;
    const int warp = tid >> 5;
    const int wr   = warp & 1;
    const int wc   = warp >> 1;
    const int row0 = blockIdx.y * 128;
    const int col0 = blockIdx.x * 128;
    const int lr = lane >> 2;
    const int lc = lane & 3;

    float acc[4][4][4];
    #pragma unroll
    for (int i = 0; i < 4; i++)
        #pragma unroll
        for (int j = 0; j < 4; j++)
            #pragma unroll
            for (int k = 0; k < 4; k++) acc[i][j][k] = 0.0f;

    for (int k0 = 0; k0 < Kn; k0 += 32) {
        #pragma unroll
        for (int i = 0; i < 4; i++) {
            int f  = tid + i * 256;
            int r  = f >> 3;
            int c4 = (f & 7) << 2;
            float4 v = *reinterpret_cast<const float4*>(
                &A[(size_t)(row0 + r) * Kn + k0 + c4]);
            float4 w;
            w.x = __uint_as_float(f2tf32(v.x));
            w.y = __uint_as_float(f2tf32(v.y));
            w.z = __uint_as_float(f2tf32(v.z));
            w.w = __uint_as_float(f2tf32(v.w));
            *reinterpret_cast<float4*>(&As[r * ASTRIDE + c4]) = w;
        }
        #pragma unroll
        for (int i = 0; i < 4; i++) {
            int f  = tid + i * 256;
            int kr = f >> 5;
            int n4 = (f & 31) << 2;
            float4 v = *reinterpret_cast<const float4*>(
                &Bm[(size_t)(k0 + kr) * Nn + col0 + n4]);
            float4 w;
            w.x = __uint_as_float(f2tf32(v.x));
            w.y = __uint_as_float(f2tf32(v.y));
            w.z = __uint_as_float(f2tf32(v.z));
            w.w = __uint_as_float(f2tf32(v.w));
            *reinterpret_cast<float4*>(&Bs[kr * BSTRIDE + n4]) = w;
        }
        __syncthreads();

        #pragma unroll
        for (int ks = 0; ks < 4; ks++) {
            const int kk = ks * 8;
            uint32_t a[4][4], b[4][2];
            #pragma unroll
            for (int mt = 0; mt < 4; mt++) {
                int m = wr * 64 + mt * 16 + lr;
                int k = kk + lc;
                a[mt][0] = __float_as_uint(As[m * ASTRIDE + k]);
                a[mt][1] = __float_as_uint(As[(m + 8) * ASTRIDE + k]);
                a[mt][2] = __float_as_uint(As[m * ASTRIDE + k + 4]);
                a[mt][3] = __float_as_uint(As[(m + 8) * ASTRIDE + k + 4]);
            }
            #pragma unroll
            for (int nt = 0; nt < 4; nt++) {
                int n = wc * 32 + nt * 8 + lr;
                int k = kk + lc;
                b[nt][0] = __float_as_uint(Bs[k * BSTRIDE + n]);
                b[nt][1] = __float_as_uint(Bs[(k + 4) * BSTRIDE + n]);
            }
            #pragma unroll
            for (int mt = 0; mt < 4; mt++)
                #pragma unroll
                for (int nt = 0; nt < 4; nt++)
                    asm volatile(
                        "mma.sync.aligned.m16n8k8.row.col.f32.tf32.tf32.f32 "
                        "{%0,%1,%2,%3}, {%4,%5,%6,%7}, {%8,%9}, {%0,%1,%2,%3};"
                        : "+f"(acc[mt][nt][0]), "+f"(acc[mt][nt][1]),
                          "+f"(acc[mt][nt][2]), "+f"(acc[mt][nt][3])
                        : "r"(a[mt][0]), "r"(a[mt][1]), "r"(a[mt][2]), "r"(a[mt][3]),
                          "r"(b[nt][0]), "r"(b[nt][1]));
        }
        __syncthreads();
    }

    #pragma unroll
    for (int mt = 0; mt < 4; mt++) {
        int r = row0 + wr * 64 + mt * 16 + lr;
        #pragma unroll
        for (int nt = 0; nt < 4; nt++) {
            int c = col0 + wc * 32 + nt * 8 + 2 * lc;
            float b0 = __ldg(&bias[c]);
            float b1 = __ldg(&bias[c + 1]);
            float2 v0 = make_float2(acc[mt][nt][0] + b0, acc[mt][nt][1] + b1);
            float2 v1 = make_float2(acc[mt][nt][2] + b0, acc[mt][nt][3] + b1);
            *reinterpret_cast<float2*>(&Cm[(size_t)r * Nn + c]) = v0;
            *reinterpret_cast<float2*>(&Cm[(size_t)(r + 8) * Nn + c]) = v1;
        }
    }
}

// ---------------------------------------------------------------------------
// Flash attention (causal) with TF32 tensor cores.
// Br=128 (8 warps x m16), Bc=64, D=64.
// smem: Qs[128][68], Ks[64][68], Vs[64][72], Ps[128][68]
// ---------------------------------------------------------------------------
#define QS_STR 68
#define VS_STR 72
#define OFF_Q  0
#define OFF_K  (128 * QS_STR)                 // 8704
#define OFF_V  (OFF_K + 64 * QS_STR)          // +4352
#define OFF_P  (OFF_V + 64 * VS_STR)          // +4608
#define FA_SMEM_FLOATS (OFF_P + 128 * QS_STR)
#define FA_SMEM_BYTES  (FA_SMEM_FLOATS * sizeof(float))

__global__ __launch_bounds__(256, 2) void flash_tf32(
    const float* __restrict__ qkv, float* __restrict__ y)
{
    extern __shared__ float sm[];
    float* Qs = sm + OFF_Q;
    float* Ks = sm + OFF_K;
    float* Vs = sm + OFF_V;
    float* Ps = sm + OFF_P;

    const int tid  = threadIdx.x;
    const int lane = tid & 31;
    const int w    = tid >> 5;      // warp 0..7 -> q rows w*16..w*16+15
    const int lr   = lane >> 2;     // 0..7
    const int lc   = lane & 3;      // 0..3
    const int bx   = blockIdx.x;
    const int h    = blockIdx.y;
    const int b    = blockIdx.z;
    const int q0   = bx * 128;

    // ---- load Q tile [128 x 64], scaled by 1/8, tf32-rounded ----
    const size_t baseQ = (size_t)(b * TT + q0) * C3 + h * DH;
    #pragma unroll
    for (int i = 0; i < 8; i++) {
        int f  = tid + i * 256;       // 0..2047 float4 slots
        int r  = f >> 4;              // 0..127
        int d4 = (f & 15) << 2;       // 0..60
        float4 v = *reinterpret_cast<const float4*>(&qkv[baseQ + (size_t)r * C3 + d4]);
        float4 t;
        t.x = __uint_as_float(f2tf32(v.x * 0.125f));
        t.y = __uint_as_float(f2tf32(v.y * 0.125f));
        t.z = __uint_as_float(f2tf32(v.z * 0.125f));
        t.w = __uint_as_float(f2tf32(v.w * 0.125f));
        *reinterpret_cast<float4*>(&Qs[r * QS_STR + d4]) = t;
    }

    float o[8][4];
    #pragma unroll
    for (int t = 0; t < 8; t++)
        #pragma unroll
        for (int j = 0; j < 4; j++) o[t][j] = 0.0f;
    float m0 = -1e30f, m1 = -1e30f, l0 = 0.0f, l1 = 0.0f;

    const int rmin = q0 + w * 16;          // warp's first q row
    const size_t baseKV = (size_t)(b * TT) * C3 + h * DH;
    const int nkt = 2 * bx + 2;

    for (int kt = 0; kt < nkt; kt++) {
        const int k0 = kt * 64;
        __syncthreads();
        // ---- load K [64x64] stride 68, V [64x64] stride 72 (tf32) ----
        #pragma unroll
        for (int i = 0; i < 4; i++) {
            int f  = tid + i * 256;
            int r  = f >> 4;              // 0..63
            int d4 = (f & 15) << 2;
            const float* src = &qkv[baseKV + (size_t)(k0 + r) * C3 + CC + d4];
            float4 v = *reinterpret_cast<const float4*>(src);
            float4 t;
            t.x = __uint_as_float(f2tf32(v.x));
            t.y = __uint_as_float(f2tf32(v.y));
            t.z = __uint_as_float(f2tf32(v.z));
            t.w = __uint_as_float(f2tf32(v.w));
            *reinterpret_cast<float4*>(&Ks[r * QS_STR + d4]) = t;
            const float* srcv = &qkv[baseKV + (size_t)(k0 + r) * C3 + 2 * CC + d4];
            float4 vv = *reinterpret_cast<const float4*>(srcv);
            float4 tv;
            tv.x = __uint_as_float(f2tf32(vv.x));
            tv.y = __uint_as_float(f2tf32(vv.y));
            tv.z = __uint_as_float(f2tf32(vv.z));
            tv.w = __uint_as_float(f2tf32(vv.w));
            *reinterpret_cast<float4*>(&Vs[r * VS_STR + d4]) = tv;
        }
        __syncthreads();

        if (k0 > rmin + 15) continue;   // tile fully masked for this warp

        // ---- S = Q @ K^T : 8 n-tiles x 8 k-steps of m16n8k8 ----
        float s[8][4];
        #pragma unroll
        for (int t = 0; t < 8; t++)
            #pragma unroll
            for (int j = 0; j < 4; j++) s[t][j] = 0.0f;

        #pragma unroll
        for (int ks = 0; ks < 8; ks++) {
            const int kk = ks * 8;
            uint32_t a[4];
            a[0] = __float_as_uint(Qs[(w * 16 + lr) * QS_STR + kk + lc]);
            a[1] = __float_as_uint(Qs[(w * 16 + lr + 8) * QS_STR + kk + lc]);
            a[2] = __float_as_uint(Qs[(w * 16 + lr) * QS_STR + kk + lc + 4]);
            a[3] = __float_as_uint(Qs[(w * 16 + lr + 8) * QS_STR + kk + lc + 4]);
            #pragma unroll
            for (int nt = 0; nt < 8; nt++) {
                uint32_t b0 = __float_as_uint(Ks[(nt * 8 + lr) * QS_STR + kk + lc]);
                uint32_t b1 = __float_as_uint(Ks[(nt * 8 + lr) * QS_STR + kk + lc + 4]);
                asm volatile(
                    "mma.sync.aligned.m16n8k8.row.col.f32.tf32.tf32.f32 "
                    "{%0,%1,%2,%3}, {%4,%5,%6,%7}, {%8,%9}, {%0,%1,%2,%3};"
                    : "+f"(s[nt][0]), "+f"(s[nt][1]), "+f"(s[nt][2]), "+f"(s[nt][3])
                    : "r"(a[0]), "r"(a[1]), "r"(a[2]), "r"(a[3]),
                      "r"(b0), "r"(b1));
            }
        }

        // ---- causal mask (only on diagonal-straddling tiles) ----
        if (k0 + 63 > rmin) {
            #pragma unroll
            for (int t = 0; t < 8; t++) {
                int c = k0 + t * 8 + 2 * lc;
                if (c > rmin + lr)          s[t][0] = -1e30f;
                if (c + 1 > rmin + lr)      s[t][1] = -1e30f;
                if (c > rmin + lr + 8)      s[t][2] = -1e30f;
                if (c + 1 > rmin + lr + 8)  s[t][3] = -1e30f;
            }
        }

        // ---- online softmax (rows lr and lr+8; quad = lanes sharing row) ----
        float mx0 = -1e30f, mx1 = -1e30f;
        #pragma unroll
        for (int t = 0; t < 8; t++) {
            mx0 = fmaxf(mx0, fmaxf(s[t][0], s[t][1]));
            mx1 = fmaxf(mx1, fmaxf(s[t][2], s[t][3]));
        }
        mx0 = fmaxf(mx0, __shfl_xor_sync(0xffffffffu, mx0, 1));
        mx0 = fmaxf(mx0, __shfl_xor_sync(0xffffffffu, mx0, 2));
        mx1 = fmaxf(mx1, __shfl_xor_sync(0xffffffffu, mx1, 1));
        mx1 = fmaxf(mx1, __shfl_xor_sync(0xffffffffu, mx1, 2));

        float mn0 = fmaxf(m0, mx0), mn1 = fmaxf(m1, mx1);
        float c0 = __expf(m0 - mn0), c1 = __expf(m1 - mn1);
        m0 = mn0; m1 = mn1;

        float rs0 = 0.0f, rs1 = 0.0f;
        #pragma unroll
        for (int t = 0; t < 8; t++) {
            float p00 = __expf(s[t][0] - m0);
            float p01 = __expf(s[t][1] - m0);
            float p10 = __expf(s[t][2] - m1);
            float p11 = __expf(s[t][3] - m1);
            rs0 += p00 + p01;
            rs1 += p10 + p11;
            float2 w0, w1;
            w0.x = __uint_as_float(f2tf32(p00));
            w0.y = __uint_as_float(f2tf32(p01));
            w1.x = __uint_as_float(f2tf32(p10));
            w1.y = __uint_as_float(f2tf32(p11));
            *reinterpret_cast<float2*>(&Ps[(w * 16 + lr) * QS_STR + t * 8 + 2 * lc]) = w0;
            *reinterpret_cast<float2*>(&Ps[(w * 16 + lr + 8) * QS_STR + t * 8 + 2 * lc]) = w1;
            o[t][0] *= c0; o[t][1] *= c0;
            o[t][2] *= c1; o[t][3] *= c1;
        }
        rs0 += __shfl_xor_sync(0xffffffffu, rs0, 1);
        rs0 += __shfl_xor_sync(0xffffffffu, rs0, 2);
        rs1 += __shfl_xor_sync(0xffffffffu, rs1, 1);
        rs1 += __shfl_xor_sync(0xffffffffu, rs1, 2);
        l0 = l0 * c0 + rs0;
        l1 = l1 * c1 + rs1;

        __syncwarp();

        // ---- O += P @ V ----
        #pragma unroll
        for (int ks = 0; ks < 8; ks++) {
            const int kk = ks * 8;
            uint32_t a[4];
            a[0] = __float_as_uint(Ps[(w * 16 + lr) * QS_STR + kk + lc]);
            a[1] = __float_as_uint(Ps[(w * 16 + lr + 8) * QS_STR + kk + lc]);
            a[2] = __float_as_uint(Ps[(w * 16 + lr) * QS_STR + kk + lc + 4]);
            a[3] = __float_as_uint(Ps[(w * 16 + lr + 8) * QS_STR + kk + lc + 4]);
            #pragma unroll
            for (int nt = 0; nt < 8; nt++) {
                uint32_t b0 = __float_as_uint(Vs[(kk + lc) * VS_STR + nt * 8 + lr]);
                uint32_t b1 = __float_as_uint(Vs[(kk + lc + 4) * VS_STR + nt * 8 + lr]);
                asm volatile(
                    "mma.sync.aligned.m16n8k8.row.col.f32.tf32.tf32.f32 "
                    "{%0,%1,%2,%3}, {%4,%5,%6,%7}, {%8,%9}, {%0,%1,%2,%3};"
                    : "+f"(o[nt][0]), "+f"(o[nt][1]), "+f"(o[nt][2]), "+f"(o[nt][3])
                    : "r"(a[0]), "r"(a[1]), "r"(a[2]), "r"(a[3]),
                      "r"(b0), "r"(b1));
            }
        }
    }

    // ---- epilogue: divide by l, write y[b, q, h*64 + d] ----
    float inv0 = 1.0f / l0, inv1 = 1.0f / l1;
    const size_t baseY = (size_t)(b * TT + q0 + w * 16) * CC + h * DH;
    #pragma unroll
    for (int t = 0; t < 8; t++) {
        int c = t * 8 + 2 * lc;
        float2 v0 = make_float2(o[t][0] * inv0, o[t][1] * inv0);
        float2 v1 = make_float2(o[t][2] * inv1, o[t][3] * inv1);
        *reinterpret_cast<float2*>(&g_y[baseY + (size_t)lr * CC + c]) = v0;
        *reinterpret_cast<float2*>(&g_y[baseY + (size_t)(lr + 8) * CC + c]) = v1;
    }
}

// ---------------------------------------------------------------------------
extern "C" void kernel_launch(void* const* d_in, const int* in_sizes, int n_in,
                              void* d_out, int out_size)
{
    const float* x      = (const float*)d_in[0];
    const float* W_attn = (const float*)d_in[1];
    const float* b_attn = (const float*)d_in[2];
    const float* W_proj = (const float*)d_in[3];
    const float* b_proj = (const float*)d_in[4];
    float* out = (float*)d_out;

    float *qkv_ptr, *y_ptr;
    cudaGetSymbolAddress((void**)&qkv_ptr, g_qkv);
    cudaGetSymbolAddress((void**)&y_ptr, g_y);

    static bool attr_set = false;
    if (!attr_set) {
        cudaFuncSetAttribute(flash_tf32,
                             cudaFuncAttributeMaxDynamicSharedMemorySize,
                             FA_SMEM_BYTES);
        attr_set = true;
    }

    sgemm_tf32<<<dim3(C3 / 128, MROWS / 128), 256>>>(
        x, W_attn, b_attn, qkv_ptr, MROWS, C3, CC);

    flash_tf32<<<dim3(TT / 128, HH, BB), 256, FA_SMEM_BYTES>>>(qkv_ptr, y_ptr);

    sgemm_tf32<<<dim3(CC / 128, MROWS / 128), 256>>>(
        y_ptr, W_proj, b_proj, out, MROWS, CC, CC);
}

// round 5
// speedup vs baseline: 3.8805x; 1.0479x over previous
#include <cuda_runtime.h>
#include <math.h>
#include <stdint.h>

#define BB 4
#define TT 2048
#define CC 1024
#define HH 16
#define DH 64
#define MROWS (BB*TT)
#define C3   (3*CC)

__device__ float g_qkv[(size_t)MROWS * C3];   // [M, 3C]
__device__ float g_y[(size_t)MROWS * CC];     // [M, C]

__device__ __forceinline__ uint32_t f2tf32(float x) {
    uint32_t r;
    asm("cvt.rna.tf32.f32 %0, %1;" : "=r"(r) : "f"(x));
    return r;
}

__device__ __forceinline__ void cpasync16(uint32_t dst_smem, const void* src) {
    asm volatile("cp.async.cg.shared.global [%0], [%1], 16;"
                 :: "r"(dst_smem), "l"(src));
}

// ---------------------------------------------------------------------------
// TF32 tensor-core SGEMM with cp.async double buffering.
// C[M,N] = A[M,K] @ B[K,N] + bias[N]
// block 256 (8 warps 2x4), tile 128x128, BK=32, warp tile 64x32.
// smem (dynamic): 2 x (A 128x36 + B 32x136) raw fp32; tf32 cvt at frag load.
// ---------------------------------------------------------------------------
#define ASTRIDE 36
#define BSTRIDE 136
#define A_FLOATS (128 * ASTRIDE)     // 4608
#define B_FLOATS (32 * BSTRIDE)      // 4352
#define STAGE_FLOATS (A_FLOATS + B_FLOATS)
#define GEMM_SMEM_BYTES (2 * STAGE_FLOATS * (int)sizeof(float))

__global__ __launch_bounds__(256, 2) void sgemm_tf32(
    const float* __restrict__ A, const float* __restrict__ Bm,
    const float* __restrict__ bias, float* __restrict__ Cm,
    int Mn, int Nn, int Kn)
{
    extern __shared__ float smg[];

    const int tid  = threadIdx.x;
    const int lane = tid & 31;
    const int warp = tid >> 5;
    const int wr   = warp & 1;
    const int wc   = warp >> 1;
    const int row0 = blockIdx.y * 128;
    const int col0 = blockIdx.x * 128;
    const int lr = lane >> 2;
    const int lc = lane & 3;

    const uint32_t smbase = (uint32_t)__cvta_generic_to_shared(smg);

    // per-thread load coordinates (4 A slots + 4 B slots)
    int ar[4], ac[4], br[4], bc[4];
    #pragma unroll
    for (int i = 0; i < 4; i++) {
        int f = tid + i * 256;
        ar[i] = f >> 3;            // 0..127
        ac[i] = (f & 7) << 2;      // 0..28
        br[i] = f >> 5;            // 0..31
        bc[i] = (f & 31) << 2;     // 0..124
    }

    // issue cp.async for stage `st`, k offset k0
    auto issue_stage = [&](int st, int k0) {
        uint32_t abase = smbase + (st * STAGE_FLOATS) * 4;
        uint32_t bbase = abase + A_FLOATS * 4;
        #pragma unroll
        for (int i = 0; i < 4; i++)
            cpasync16(abase + (ar[i] * ASTRIDE + ac[i]) * 4,
                      &A[(size_t)(row0 + ar[i]) * Kn + k0 + ac[i]]);
        #pragma unroll
        for (int i = 0; i < 4; i++)
            cpasync16(bbase + (br[i] * BSTRIDE + bc[i]) * 4,
                      &Bm[(size_t)(k0 + br[i]) * Nn + col0 + bc[i]]);
        asm volatile("cp.async.commit_group;");
    };

    float acc[4][4][4];
    #pragma unroll
    for (int i = 0; i < 4; i++)
        #pragma unroll
        for (int j = 0; j < 4; j++)
            #pragma unroll
            for (int k = 0; k < 4; k++) acc[i][j][k] = 0.0f;

    const int niter = Kn / 32;
    issue_stage(0, 0);

    for (int it = 0; it < niter; it++) {
        if (it + 1 < niter) {
            issue_stage((it + 1) & 1, (it + 1) * 32);
            asm volatile("cp.async.wait_group 1;");
        } else {
            asm volatile("cp.async.wait_group 0;");
        }
        __syncthreads();

        const float* As = smg + (it & 1) * STAGE_FLOATS;
        const float* Bs = As + A_FLOATS;

        #pragma unroll
        for (int ks = 0; ks < 4; ks++) {
            const int kk = ks * 8;
            uint32_t a[4][4], b[4][2];
            #pragma unroll
            for (int mt = 0; mt < 4; mt++) {
                int m = wr * 64 + mt * 16 + lr;
                int k = kk + lc;
                a[mt][0] = f2tf32(As[m * ASTRIDE + k]);
                a[mt][1] = f2tf32(As[(m + 8) * ASTRIDE + k]);
                a[mt][2] = f2tf32(As[m * ASTRIDE + k + 4]);
                a[mt][3] = f2tf32(As[(m + 8) * ASTRIDE + k + 4]);
            }
            #pragma unroll
            for (int nt = 0; nt < 4; nt++) {
                int n = wc * 32 + nt * 8 + lr;
                int k = kk + lc;
                b[nt][0] = f2tf32(Bs[k * BSTRIDE + n]);
                b[nt][1] = f2tf32(Bs[(k + 4) * BSTRIDE + n]);
            }
            #pragma unroll
            for (int mt = 0; mt < 4; mt++)
                #pragma unroll
                for (int nt = 0; nt < 4; nt++)
                    asm volatile(
                        "mma.sync.aligned.m16n8k8.row.col.f32.tf32.tf32.f32 "
                        "{%0,%1,%2,%3}, {%4,%5,%6,%7}, {%8,%9}, {%0,%1,%2,%3};"
                        : "+f"(acc[mt][nt][0]), "+f"(acc[mt][nt][1]),
                          "+f"(acc[mt][nt][2]), "+f"(acc[mt][nt][3])
                        : "r"(a[mt][0]), "r"(a[mt][1]), "r"(a[mt][2]), "r"(a[mt][3]),
                          "r"(b[nt][0]), "r"(b[nt][1]));
        }
        __syncthreads();
    }

    #pragma unroll
    for (int mt = 0; mt < 4; mt++) {
        int r = row0 + wr * 64 + mt * 16 + lr;
        #pragma unroll
        for (int nt = 0; nt < 4; nt++) {
            int c = col0 + wc * 32 + nt * 8 + 2 * lc;
            float b0 = __ldg(&bias[c]);
            float b1 = __ldg(&bias[c + 1]);
            float2 v0 = make_float2(acc[mt][nt][0] + b0, acc[mt][nt][1] + b1);
            float2 v1 = make_float2(acc[mt][nt][2] + b0, acc[mt][nt][3] + b1);
            *reinterpret_cast<float2*>(&Cm[(size_t)r * Nn + c]) = v0;
            *reinterpret_cast<float2*>(&Cm[(size_t)(r + 8) * Nn + c]) = v1;
        }
    }
}

// ---------------------------------------------------------------------------
// Flash attention (causal) with TF32 tensor cores (unchanged from R4).
// Br=128 (8 warps x m16), Bc=64, D=64.
// ---------------------------------------------------------------------------
#define QS_STR 68
#define VS_STR 72
#define OFF_Q  0
#define OFF_K  (128 * QS_STR)
#define OFF_V  (OFF_K + 64 * QS_STR)
#define OFF_P  (OFF_V + 64 * VS_STR)
#define FA_SMEM_FLOATS (OFF_P + 128 * QS_STR)
#define FA_SMEM_BYTES  (FA_SMEM_FLOATS * sizeof(float))

__global__ __launch_bounds__(256, 2) void flash_tf32(
    const float* __restrict__ qkv, float* __restrict__ y)
{
    extern __shared__ float sm[];
    float* Qs = sm + OFF_Q;
    float* Ks = sm + OFF_K;
    float* Vs = sm + OFF_V;
    float* Ps = sm + OFF_P;

    const int tid  = threadIdx.x;
    const int lane = tid & 31;
    const int w    = tid >> 5;
    const int lr   = lane >> 2;
    const int lc   = lane & 3;
    const int bx   = blockIdx.x;
    const int h    = blockIdx.y;
    const int b    = blockIdx.z;
    const int q0   = bx * 128;

    const size_t baseQ = (size_t)(b * TT + q0) * C3 + h * DH;
    #pragma unroll
    for (int i = 0; i < 8; i++) {
        int f  = tid + i * 256;
        int r  = f >> 4;
        int d4 = (f & 15) << 2;
        float4 v = *reinterpret_cast<const float4*>(&qkv[baseQ + (size_t)r * C3 + d4]);
        float4 t;
        t.x = __uint_as_float(f2tf32(v.x * 0.125f));
        t.y = __uint_as_float(f2tf32(v.y * 0.125f));
        t.z = __uint_as_float(f2tf32(v.z * 0.125f));
        t.w = __uint_as_float(f2tf32(v.w * 0.125f));
        *reinterpret_cast<float4*>(&Qs[r * QS_STR + d4]) = t;
    }

    float o[8][4];
    #pragma unroll
    for (int t = 0; t < 8; t++)
        #pragma unroll
        for (int j = 0; j < 4; j++) o[t][j] = 0.0f;
    float m0 = -1e30f, m1 = -1e30f, l0 = 0.0f, l1 = 0.0f;

    const int rmin = q0 + w * 16;
    const size_t baseKV = (size_t)(b * TT) * C3 + h * DH;
    const int nkt = 2 * bx + 2;

    for (int kt = 0; kt < nkt; kt++) {
        const int k0 = kt * 64;
        __syncthreads();
        #pragma unroll
        for (int i = 0; i < 4; i++) {
            int f  = tid + i * 256;
            int r  = f >> 4;
            int d4 = (f & 15) << 2;
            const float* src = &qkv[baseKV + (size_t)(k0 + r) * C3 + CC + d4];
            float4 v = *reinterpret_cast<const float4*>(src);
            float4 t;
            t.x = __uint_as_float(f2tf32(v.x));
            t.y = __uint_as_float(f2tf32(v.y));
            t.z = __uint_as_float(f2tf32(v.z));
            t.w = __uint_as_float(f2tf32(v.w));
            *reinterpret_cast<float4*>(&Ks[r * QS_STR + d4]) = t;
            const float* srcv = &qkv[baseKV + (size_t)(k0 + r) * C3 + 2 * CC + d4];
            float4 vv = *reinterpret_cast<const float4*>(srcv);
            float4 tv;
            tv.x = __uint_as_float(f2tf32(vv.x));
            tv.y = __uint_as_float(f2tf32(vv.y));
            tv.z = __uint_as_float(f2tf32(vv.z));
            tv.w = __uint_as_float(f2tf32(vv.w));
            *reinterpret_cast<float4*>(&Vs[r * VS_STR + d4]) = tv;
        }
        __syncthreads();

        if (k0 > rmin + 15) continue;

        float s[8][4];
        #pragma unroll
        for (int t = 0; t < 8; t++)
            #pragma unroll
            for (int j = 0; j < 4; j++) s[t][j] = 0.0f;

        #pragma unroll
        for (int ks = 0; ks < 8; ks++) {
            const int kk = ks * 8;
            uint32_t a[4];
            a[0] = __float_as_uint(Qs[(w * 16 + lr) * QS_STR + kk + lc]);
            a[1] = __float_as_uint(Qs[(w * 16 + lr + 8) * QS_STR + kk + lc]);
            a[2] = __float_as_uint(Qs[(w * 16 + lr) * QS_STR + kk + lc + 4]);
            a[3] = __float_as_uint(Qs[(w * 16 + lr + 8) * QS_STR + kk + lc + 4]);
            #pragma unroll
            for (int nt = 0; nt < 8; nt++) {
                uint32_t b0 = __float_as_uint(Ks[(nt * 8 + lr) * QS_STR + kk + lc]);
                uint32_t b1 = __float_as_uint(Ks[(nt * 8 + lr) * QS_STR + kk + lc + 4]);
                asm volatile(
                    "mma.sync.aligned.m16n8k8.row.col.f32.tf32.tf32.f32 "
                    "{%0,%1,%2,%3}, {%4,%5,%6,%7}, {%8,%9}, {%0,%1,%2,%3};"
                    : "+f"(s[nt][0]), "+f"(s[nt][1]), "+f"(s[nt][2]), "+f"(s[nt][3])
                    : "r"(a[0]), "r"(a[1]), "r"(a[2]), "r"(a[3]),
                      "r"(b0), "r"(b1));
            }
        }

        if (k0 + 63 > rmin) {
            #pragma unroll
            for (int t = 0; t < 8; t++) {
                int c = k0 + t * 8 + 2 * lc;
                if (c > rmin + lr)          s[t][0] = -1e30f;
                if (c + 1 > rmin + lr)      s[t][1] = -1e30f;
                if (c > rmin + lr + 8)      s[t][2] = -1e30f;
                if (c + 1 > rmin + lr + 8)  s[t][3] = -1e30f;
            }
        }

        float mx0 = -1e30f, mx1 = -1e30f;
        #pragma unroll
        for (int t = 0; t < 8; t++) {
            mx0 = fmaxf(mx0, fmaxf(s[t][0], s[t][1]));
            mx1 = fmaxf(mx1, fmaxf(s[t][2], s[t][3]));
        }
        mx0 = fmaxf(mx0, __shfl_xor_sync(0xffffffffu, mx0, 1));
        mx0 = fmaxf(mx0, __shfl_xor_sync(0xffffffffu, mx0, 2));
        mx1 = fmaxf(mx1, __shfl_xor_sync(0xffffffffu, mx1, 1));
        mx1 = fmaxf(mx1, __shfl_xor_sync(0xffffffffu, mx1, 2));

        float mn0 = fmaxf(m0, mx0), mn1 = fmaxf(m1, mx1);
        float c0 = __expf(m0 - mn0), c1 = __expf(m1 - mn1);
        m0 = mn0; m1 = mn1;

        float rs0 = 0.0f, rs1 = 0.0f;
        #pragma unroll
        for (int t = 0; t < 8; t++) {
            float p00 = __expf(s[t][0] - m0);
            float p01 = __expf(s[t][1] - m0);
            float p10 = __expf(s[t][2] - m1);
            float p11 = __expf(s[t][3] - m1);
            rs0 += p00 + p01;
            rs1 += p10 + p11;
            float2 w0, w1;
            w0.x = __uint_as_float(f2tf32(p00));
            w0.y = __uint_as_float(f2tf32(p01));
            w1.x = __uint_as_float(f2tf32(p10));
            w1.y = __uint_as_float(f2tf32(p11));
            *reinterpret_cast<float2*>(&Ps[(w * 16 + lr) * QS_STR + t * 8 + 2 * lc]) = w0;
            *reinterpret_cast<float2*>(&Ps[(w * 16 + lr + 8) * QS_STR + t * 8 + 2 * lc]) = w1;
            o[t][0] *= c0; o[t][1] *= c0;
            o[t][2] *= c1; o[t][3] *= c1;
        }
        rs0 += __shfl_xor_sync(0xffffffffu, rs0, 1);
        rs0 += __shfl_xor_sync(0xffffffffu, rs0, 2);
        rs1 += __shfl_xor_sync(0xffffffffu, rs1, 1);
        rs1 += __shfl_xor_sync(0xffffffffu, rs1, 2);
        l0 = l0 * c0 + rs0;
        l1 = l1 * c1 + rs1;

        __syncwarp();

        #pragma unroll
        for (int ks = 0; ks < 8; ks++) {
            const int kk = ks * 8;
            uint32_t a[4];
            a[0] = __float_as_uint(Ps[(w * 16 + lr) * QS_STR + kk + lc]);
            a[1] = __float_as_uint(Ps[(w * 16 + lr + 8) * QS_STR + kk + lc]);
            a[2] = __float_as_uint(Ps[(w * 16 + lr) * QS_STR + kk + lc + 4]);
            a[3] = __float_as_uint(Ps[(w * 16 + lr + 8) * QS_STR + kk + lc + 4]);
            #pragma unroll
            for (int nt = 0; nt < 8; nt++) {
                uint32_t b0 = __float_as_uint(Vs[(kk + lc) * VS_STR + nt * 8 + lr]);
                uint32_t b1 = __float_as_uint(Vs[(kk + lc + 4) * VS_STR + nt * 8 + lr]);
                asm volatile(
                    "mma.sync.aligned.m16n8k8.row.col.f32.tf32.tf32.f32 "
                    "{%0,%1,%2,%3}, {%4,%5,%6,%7}, {%8,%9}, {%0,%1,%2,%3};"
                    : "+f"(o[nt][0]), "+f"(o[nt][1]), "+f"(o[nt][2]), "+f"(o[nt][3])
                    : "r"(a[0]), "r"(a[1]), "r"(a[2]), "r"(a[3]),
                      "r"(b0), "r"(b1));
            }
        }
    }

    float inv0 = 1.0f / l0, inv1 = 1.0f / l1;
    const size_t baseY = (size_t)(b * TT + q0 + w * 16) * CC + h * DH;
    #pragma unroll
    for (int t = 0; t < 8; t++) {
        int c = t * 8 + 2 * lc;
        float2 v0 = make_float2(o[t][0] * inv0, o[t][1] * inv0);
        float2 v1 = make_float2(o[t][2] * inv1, o[t][3] * inv1);
        *reinterpret_cast<float2*>(&g_y[baseY + (size_t)lr * CC + c]) = v0;
        *reinterpret_cast<float2*>(&g_y[baseY + (size_t)(lr + 8) * CC + c]) = v1;
    }
}

// ---------------------------------------------------------------------------
extern "C" void kernel_launch(void* const* d_in, const int* in_sizes, int n_in,
                              void* d_out, int out_size)
{
    const float* x      = (const float*)d_in[0];
    const float* W_attn = (const float*)d_in[1];
    const float* b_attn = (const float*)d_in[2];
    const float* W_proj = (const float*)d_in[3];
    const float* b_proj = (const float*)d_in[4];
    float* out = (float*)d_out;

    float *qkv_ptr, *y_ptr;
    cudaGetSymbolAddress((void**)&qkv_ptr, g_qkv);
    cudaGetSymbolAddress((void**)&y_ptr, g_y);

    static bool attr_set = false;
    if (!attr_set) {
        cudaFuncSetAttribute(flash_tf32,
                             cudaFuncAttributeMaxDynamicSharedMemorySize,
                             FA_SMEM_BYTES);
        cudaFuncSetAttribute(sgemm_tf32,
                             cudaFuncAttributeMaxDynamicSharedMemorySize,
                             GEMM_SMEM_BYTES);
        attr_set = true;
    }

    sgemm_tf32<<<dim3(C3 / 128, MROWS / 128), 256, GEMM_SMEM_BYTES>>>(
        x, W_attn, b_attn, qkv_ptr, MROWS, C3, CC);

    flash_tf32<<<dim3(TT / 128, HH, BB), 256, FA_SMEM_BYTES>>>(qkv_ptr, y_ptr);

    sgemm_tf32<<<dim3(CC / 128, MROWS / 128), 256, GEMM_SMEM_BYTES>>>(
        y_ptr, W_proj, b_proj, out, MROWS, CC, CC);
}

// round 7
// speedup vs baseline: 3.9535x; 1.0188x over previous
#include <cuda_runtime.h>
#include <math.h>
#include <stdint.h>

#define BB 4
#define TT 2048
#define CC 1024
#define HH 16
#define DH 64
#define MROWS (BB*TT)
#define C3   (3*CC)

// scratch (no cudaMalloc allowed)
__device__ float g_qkv[(size_t)MROWS * C3];    // [M, 3C] tf32-rounded
__device__ float g_y[(size_t)MROWS * CC];      // [M, C]  tf32-rounded
__device__ float g_xr[(size_t)MROWS * CC];     // x, tf32-rounded
__device__ float g_war[(size_t)CC * C3];       // W_attn, tf32-rounded
__device__ float g_wpr[(size_t)CC * CC];       // W_proj, tf32-rounded

__device__ __forceinline__ uint32_t f2tf32(float x) {
    uint32_t r;
    asm("cvt.rna.tf32.f32 %0, %1;" : "=r"(r) : "f"(x));
    return r;
}

__device__ __forceinline__ void cpasync16(uint32_t dst_smem, const void* src) {
    asm volatile("cp.async.cg.shared.global [%0], [%1], 16;"
                 :: "r"(dst_smem), "l"(src));
}

// ========================== prep: tf32-round ===============================
__global__ void prep_round(const float* __restrict__ src, float* __restrict__ dst,
                           int n4) {
    int i = blockIdx.x * blockDim.x + threadIdx.x;
    if (i < n4) {
        float4 v = reinterpret_cast<const float4*>(src)[i];
        float4 w;
        w.x = __uint_as_float(f2tf32(v.x));
        w.y = __uint_as_float(f2tf32(v.y));
        w.z = __uint_as_float(f2tf32(v.z));
        w.w = __uint_as_float(f2tf32(v.w));
        reinterpret_cast<float4*>(dst)[i] = w;
    }
}

// ---------------------------------------------------------------------------
// TF32 tensor-core SGEMM with cp.async double buffering.
// Inputs already tf32-rounded -> NO cvt in the hot loop.
// C[M,N] = A[M,K] @ B[K,N] + bias[N]; optionally tf32-round the output.
// block 256 (8 warps 2x4), tile 128x128, BK=32, warp tile 64x32.
// ---------------------------------------------------------------------------
#define ASTRIDE 36
#define BSTRIDE 136
#define A_FLOATS (128 * ASTRIDE)
#define B_FLOATS (32 * BSTRIDE)
#define STAGE_FLOATS (A_FLOATS + B_FLOATS)
#define GEMM_SMEM_BYTES (2 * STAGE_FLOATS * (int)sizeof(float))

__global__ __launch_bounds__(256, 2) void sgemm_tf32(
    const float* __restrict__ A, const float* __restrict__ Bm,
    const float* __restrict__ bias, float* __restrict__ Cm,
    int Mn, int Nn, int Kn, int round_out)
{
    extern __shared__ float smg[];

    const int tid  = threadIdx.x;
    const int lane = tid & 31;
    const int warp = tid >> 5;
    const int wr   = warp & 1;
    const int wc   = warp >> 1;
    const int row0 = blockIdx.y * 128;
    const int col0 = blockIdx.x * 128;
    const int lr = lane >> 2;
    const int lc = lane & 3;

    const uint32_t smbase = (uint32_t)__cvta_generic_to_shared(smg);

    int ar[4], ac[4], br[4], bc[4];
    #pragma unroll
    for (int i = 0; i < 4; i++) {
        int f = tid + i * 256;
        ar[i] = f >> 3;
        ac[i] = (f & 7) << 2;
        br[i] = f >> 5;
        bc[i] = (f & 31) << 2;
    }

    auto issue_stage = [&](int st, int k0) {
        uint32_t abase = smbase + (st * STAGE_FLOATS) * 4;
        uint32_t bbase = abase + A_FLOATS * 4;
        #pragma unroll
        for (int i = 0; i < 4; i++)
            cpasync16(abase + (ar[i] * ASTRIDE + ac[i]) * 4,
                      &A[(size_t)(row0 + ar[i]) * Kn + k0 + ac[i]]);
        #pragma unroll
        for (int i = 0; i < 4; i++)
            cpasync16(bbase + (br[i] * BSTRIDE + bc[i]) * 4,
                      &Bm[(size_t)(k0 + br[i]) * Nn + col0 + bc[i]]);
        asm volatile("cp.async.commit_group;");
    };

    float acc[4][4][4];
    #pragma unroll
    for (int i = 0; i < 4; i++)
        #pragma unroll
        for (int j = 0; j < 4; j++)
            #pragma unroll
            for (int k = 0; k < 4; k++) acc[i][j][k] = 0.0f;

    const int niter = Kn / 32;
    issue_stage(0, 0);

    for (int it = 0; it < niter; it++) {
        if (it + 1 < niter) {
            issue_stage((it + 1) & 1, (it + 1) * 32);
            asm volatile("cp.async.wait_group 1;");
        } else {
            asm volatile("cp.async.wait_group 0;");
        }
        __syncthreads();

        const float* As = smg + (it & 1) * STAGE_FLOATS;
        const float* Bs = As + A_FLOATS;

        #pragma unroll
        for (int ks = 0; ks < 4; ks++) {
            const int kk = ks * 8;
            uint32_t a[4][4], b[4][2];
            #pragma unroll
            for (int mt = 0; mt < 4; mt++) {
                int m = wr * 64 + mt * 16 + lr;
                int k = kk + lc;
                a[mt][0] = __float_as_uint(As[m * ASTRIDE + k]);
                a[mt][1] = __float_as_uint(As[(m + 8) * ASTRIDE + k]);
                a[mt][2] = __float_as_uint(As[m * ASTRIDE + k + 4]);
                a[mt][3] = __float_as_uint(As[(m + 8) * ASTRIDE + k + 4]);
            }
            #pragma unroll
            for (int nt = 0; nt < 4; nt++) {
                int n = wc * 32 + nt * 8 + lr;
                int k = kk + lc;
                b[nt][0] = __float_as_uint(Bs[k * BSTRIDE + n]);
                b[nt][1] = __float_as_uint(Bs[(k + 4) * BSTRIDE + n]);
            }
            #pragma unroll
            for (int mt = 0; mt < 4; mt++)
                #pragma unroll
                for (int nt = 0; nt < 4; nt++)
                    asm volatile(
                        "mma.sync.aligned.m16n8k8.row.col.f32.tf32.tf32.f32 "
                        "{%0,%1,%2,%3}, {%4,%5,%6,%7}, {%8,%9}, {%0,%1,%2,%3};"
                        : "+f"(acc[mt][nt][0]), "+f"(acc[mt][nt][1]),
                          "+f"(acc[mt][nt][2]), "+f"(acc[mt][nt][3])
                        : "r"(a[mt][0]), "r"(a[mt][1]), "r"(a[mt][2]), "r"(a[mt][3]),
                          "r"(b[nt][0]), "r"(b[nt][1]));
        }
        __syncthreads();
    }

    #pragma unroll
    for (int mt = 0; mt < 4; mt++) {
        int r = row0 + wr * 64 + mt * 16 + lr;
        #pragma unroll
        for (int nt = 0; nt < 4; nt++) {
            int c = col0 + wc * 32 + nt * 8 + 2 * lc;
            float b0 = __ldg(&bias[c]);
            float b1 = __ldg(&bias[c + 1]);
            float2 v0 = make_float2(acc[mt][nt][0] + b0, acc[mt][nt][1] + b1);
            float2 v1 = make_float2(acc[mt][nt][2] + b0, acc[mt][nt][3] + b1);
            if (round_out) {
                v0.x = __uint_as_float(f2tf32(v0.x));
                v0.y = __uint_as_float(f2tf32(v0.y));
                v1.x = __uint_as_float(f2tf32(v1.x));
                v1.y = __uint_as_float(f2tf32(v1.y));
            }
            *reinterpret_cast<float2*>(&Cm[(size_t)r * Nn + c]) = v0;
            *reinterpret_cast<float2*>(&Cm[(size_t)(r + 8) * Nn + c]) = v1;
        }
    }
}

// ---------------------------------------------------------------------------
// Flash attention (causal), TF32 mma.sync. qkv already tf32-rounded:
// Q load = plain copy * 0.125 (exact), K/V loads = plain copies.
// Br=128 (8 warps x m16), Bc=64, D=64.
// ---------------------------------------------------------------------------
#define QS_STR 68
#define VS_STR 72
#define OFF_Q  0
#define OFF_K  (128 * QS_STR)
#define OFF_V  (OFF_K + 64 * QS_STR)
#define OFF_P  (OFF_V + 64 * VS_STR)
#define FA_SMEM_FLOATS (OFF_P + 128 * QS_STR)
#define FA_SMEM_BYTES  (FA_SMEM_FLOATS * sizeof(float))

__global__ __launch_bounds__(256, 2) void flash_tf32(
    const float* __restrict__ qkv, float* __restrict__ y)
{
    extern __shared__ float sm[];
    float* Qs = sm + OFF_Q;
    float* Ks = sm + OFF_K;
    float* Vs = sm + OFF_V;
    float* Ps = sm + OFF_P;

    const int tid  = threadIdx.x;
    const int lane = tid & 31;
    const int w    = tid >> 5;
    const int lr   = lane >> 2;
    const int lc   = lane & 3;
    const int bx   = blockIdx.x;
    const int h    = blockIdx.y;
    const int b    = blockIdx.z;
    const int q0   = bx * 128;

    const size_t baseQ = (size_t)(b * TT + q0) * C3 + h * DH;
    #pragma unroll
    for (int i = 0; i < 8; i++) {
        int f  = tid + i * 256;
        int r  = f >> 4;
        int d4 = (f & 15) << 2;
        float4 v = *reinterpret_cast<const float4*>(&qkv[baseQ + (size_t)r * C3 + d4]);
        float4 t;
        t.x = v.x * 0.125f; t.y = v.y * 0.125f;
        t.z = v.z * 0.125f; t.w = v.w * 0.125f;
        *reinterpret_cast<float4*>(&Qs[r * QS_STR + d4]) = t;
    }

    float o[8][4];
    #pragma unroll
    for (int t = 0; t < 8; t++)
        #pragma unroll
        for (int j = 0; j < 4; j++) o[t][j] = 0.0f;
    float m0 = -1e30f, m1 = -1e30f, l0 = 0.0f, l1 = 0.0f;

    const int rmin = q0 + w * 16;
    const size_t baseKV = (size_t)(b * TT) * C3 + h * DH;
    const int nkt = 2 * bx + 2;

    for (int kt = 0; kt < nkt; kt++) {
        const int k0 = kt * 64;
        __syncthreads();
        #pragma unroll
        for (int i = 0; i < 4; i++) {
            int f  = tid + i * 256;
            int r  = f >> 4;
            int d4 = (f & 15) << 2;
            *reinterpret_cast<float4*>(&Ks[r * QS_STR + d4]) =
                *reinterpret_cast<const float4*>(
                    &qkv[baseKV + (size_t)(k0 + r) * C3 + CC + d4]);
            *reinterpret_cast<float4*>(&Vs[r * VS_STR + d4]) =
                *reinterpret_cast<const float4*>(
                    &qkv[baseKV + (size_t)(k0 + r) * C3 + 2 * CC + d4]);
        }
        __syncthreads();

        if (k0 > rmin + 15) continue;

        float s[8][4];
        #pragma unroll
        for (int t = 0; t < 8; t++)
            #pragma unroll
            for (int j = 0; j < 4; j++) s[t][j] = 0.0f;

        #pragma unroll
        for (int ks = 0; ks < 8; ks++) {
            const int kk = ks * 8;
            uint32_t a[4];
            a[0] = __float_as_uint(Qs[(w * 16 + lr) * QS_STR + kk + lc]);
            a[1] = __float_as_uint(Qs[(w * 16 + lr + 8) * QS_STR + kk + lc]);
            a[2] = __float_as_uint(Qs[(w * 16 + lr) * QS_STR + kk + lc + 4]);
            a[3] = __float_as_uint(Qs[(w * 16 + lr + 8) * QS_STR + kk + lc + 4]);
            #pragma unroll
            for (int nt = 0; nt < 8; nt++) {
                uint32_t b0 = __float_as_uint(Ks[(nt * 8 + lr) * QS_STR + kk + lc]);
                uint32_t b1 = __float_as_uint(Ks[(nt * 8 + lr) * QS_STR + kk + lc + 4]);
                asm volatile(
                    "mma.sync.aligned.m16n8k8.row.col.f32.tf32.tf32.f32 "
                    "{%0,%1,%2,%3}, {%4,%5,%6,%7}, {%8,%9}, {%0,%1,%2,%3};"
                    : "+f"(s[nt][0]), "+f"(s[nt][1]), "+f"(s[nt][2]), "+f"(s[nt][3])
                    : "r"(a[0]), "r"(a[1]), "r"(a[2]), "r"(a[3]),
                      "r"(b0), "r"(b1));
            }
        }

        if (k0 + 63 > rmin) {
            #pragma unroll
            for (int t = 0; t < 8; t++) {
                int c = k0 + t * 8 + 2 * lc;
                if (c > rmin + lr)          s[t][0] = -1e30f;
                if (c + 1 > rmin + lr)      s[t][1] = -1e30f;
                if (c > rmin + lr + 8)      s[t][2] = -1e30f;
                if (c + 1 > rmin + lr + 8)  s[t][3] = -1e30f;
            }
        }

        float mx0 = -1e30f, mx1 = -1e30f;
        #pragma unroll
        for (int t = 0; t < 8; t++) {
            mx0 = fmaxf(mx0, fmaxf(s[t][0], s[t][1]));
            mx1 = fmaxf(mx1, fmaxf(s[t][2], s[t][3]));
        }
        mx0 = fmaxf(mx0, __shfl_xor_sync(0xffffffffu, mx0, 1));
        mx0 = fmaxf(mx0, __shfl_xor_sync(0xffffffffu, mx0, 2));
        mx1 = fmaxf(mx1, __shfl_xor_sync(0xffffffffu, mx1, 1));
        mx1 = fmaxf(mx1, __shfl_xor_sync(0xffffffffu, mx1, 2));

        float mn0 = fmaxf(m0, mx0), mn1 = fmaxf(m1, mx1);
        float c0 = __expf(m0 - mn0), c1 = __expf(m1 - mn1);
        m0 = mn0; m1 = mn1;

        float rs0 = 0.0f, rs1 = 0.0f;
        #pragma unroll
        for (int t = 0; t < 8; t++) {
            float p00 = __expf(s[t][0] - m0);
            float p01 = __expf(s[t][1] - m0);
            float p10 = __expf(s[t][2] - m1);
            float p11 = __expf(s[t][3] - m1);
            rs0 += p00 + p01;
            rs1 += p10 + p11;
            float2 w0, w1;
            w0.x = __uint_as_float(f2tf32(p00));
            w0.y = __uint_as_float(f2tf32(p01));
            w1.x = __uint_as_float(f2tf32(p10));
            w1.y = __uint_as_float(f2tf32(p11));
            *reinterpret_cast<float2*>(&Ps[(w * 16 + lr) * QS_STR + t * 8 + 2 * lc]) = w0;
            *reinterpret_cast<float2*>(&Ps[(w * 16 + lr + 8) * QS_STR + t * 8 + 2 * lc]) = w1;
            o[t][0] *= c0; o[t][1] *= c0;
            o[t][2] *= c1; o[t][3] *= c1;
        }
        rs0 += __shfl_xor_sync(0xffffffffu, rs0, 1);
        rs0 += __shfl_xor_sync(0xffffffffu, rs0, 2);
        rs1 += __shfl_xor_sync(0xffffffffu, rs1, 1);
        rs1 += __shfl_xor_sync(0xffffffffu, rs1, 2);
        l0 = l0 * c0 + rs0;
        l1 = l1 * c1 + rs1;

        __syncwarp();

        #pragma unroll
        for (int ks = 0; ks < 8; ks++) {
            const int kk = ks * 8;
            uint32_t a[4];
            a[0] = __float_as_uint(Ps[(w * 16 + lr) * QS_STR + kk + lc]);
            a[1] = __float_as_uint(Ps[(w * 16 + lr + 8) * QS_STR + kk + lc]);
            a[2] = __float_as_uint(Ps[(w * 16 + lr) * QS_STR + kk + lc + 4]);
            a[3] = __float_as_uint(Ps[(w * 16 + lr + 8) * QS_STR + kk + lc + 4]);
            #pragma unroll
            for (int nt = 0; nt < 8; nt++) {
                uint32_t b0 = __float_as_uint(Vs[(kk + lc) * VS_STR + nt * 8 + lr]);
                uint32_t b1 = __float_as_uint(Vs[(kk + lc + 4) * VS_STR + nt * 8 + lr]);
                asm volatile(
                    "mma.sync.aligned.m16n8k8.row.col.f32.tf32.tf32.f32 "
                    "{%0,%1,%2,%3}, {%4,%5,%6,%7}, {%8,%9}, {%0,%1,%2,%3};"
                    : "+f"(o[nt][0]), "+f"(o[nt][1]), "+f"(o[nt][2]), "+f"(o[nt][3])
                    : "r"(a[0]), "r"(a[1]), "r"(a[2]), "r"(a[3]),
                      "r"(b0), "r"(b1));
            }
        }
    }

    float inv0 = 1.0f / l0, inv1 = 1.0f / l1;
    const size_t baseY = (size_t)(b * TT + q0 + w * 16) * CC + h * DH;
    #pragma unroll
    for (int t = 0; t < 8; t++) {
        int c = t * 8 + 2 * lc;
        float2 v0, v1;
        v0.x = __uint_as_float(f2tf32(o[t][0] * inv0));
        v0.y = __uint_as_float(f2tf32(o[t][1] * inv0));
        v1.x = __uint_as_float(f2tf32(o[t][2] * inv1));
        v1.y = __uint_as_float(f2tf32(o[t][3] * inv1));
        *reinterpret_cast<float2*>(&g_y[baseY + (size_t)lr * CC + c]) = v0;
        *reinterpret_cast<float2*>(&g_y[baseY + (size_t)(lr + 8) * CC + c]) = v1;
    }
}

// ---------------------------------------------------------------------------
extern "C" void kernel_launch(void* const* d_in, const int* in_sizes, int n_in,
                              void* d_out, int out_size)
{
    const float* x      = (const float*)d_in[0];
    const float* W_attn = (const float*)d_in[1];
    const float* b_attn = (const float*)d_in[2];
    const float* W_proj = (const float*)d_in[3];
    const float* b_proj = (const float*)d_in[4];
    float* out = (float*)d_out;

    float *qkv_ptr, *y_ptr, *xr_ptr, *war_ptr, *wpr_ptr;
    cudaGetSymbolAddress((void**)&qkv_ptr, g_qkv);
    cudaGetSymbolAddress((void**)&y_ptr, g_y);
    cudaGetSymbolAddress((void**)&xr_ptr, g_xr);
    cudaGetSymbolAddress((void**)&war_ptr, g_war);
    cudaGetSymbolAddress((void**)&wpr_ptr, g_wpr);

    static bool attr_set = false;
    if (!attr_set) {
        cudaFuncSetAttribute(flash_tf32,
                             cudaFuncAttributeMaxDynamicSharedMemorySize,
                             FA_SMEM_BYTES);
        cudaFuncSetAttribute(sgemm_tf32,
                             cudaFuncAttributeMaxDynamicSharedMemorySize,
                             GEMM_SMEM_BYTES);
        attr_set = true;
    }

    // prep: tf32-round inputs once (pure-bandwidth kernels)
    prep_round<<<(MROWS * CC / 4 + 255) / 256, 256>>>(x, xr_ptr, MROWS * CC / 4);
    prep_round<<<(CC * C3 / 4 + 255) / 256, 256>>>(W_attn, war_ptr, CC * C3 / 4);
    prep_round<<<(CC * CC / 4 + 255) / 256, 256>>>(W_proj, wpr_ptr, CC * CC / 4);

    // 1) qkv = x @ W_attn + b_attn  (output tf32-rounded)
    sgemm_tf32<<<dim3(C3 / 128, MROWS / 128), 256, GEMM_SMEM_BYTES>>>(
        xr_ptr, war_ptr, b_attn, qkv_ptr, MROWS, C3, CC, 1);

    // 2) causal flash attention -> g_y (tf32-rounded)
    flash_tf32<<<dim3(TT / 128, HH, BB), 256, FA_SMEM_BYTES>>>(qkv_ptr, y_ptr);

    // 3) out = y @ W_proj + b_proj  (full fp32 output)
    sgemm_tf32<<<dim3(CC / 128, MROWS / 128), 256, GEMM_SMEM_BYTES>>>(
        y_ptr, wpr_ptr, b_proj, out, MROWS, CC, CC, 0);
}

// round 8
// speedup vs baseline: 7.1964x; 1.8203x over previous
#include <cuda_runtime.h>
#include <cuda_fp16.h>
#include <math.h>
#include <stdint.h>

#define BB 4
#define TT 2048
#define CC 1024
#define HH 16
#define DH 64
#define MROWS (BB*TT)
#define C3   (3*CC)

// scratch (no cudaMalloc allowed)
__device__ __half g_qkv[(size_t)MROWS * C3];   // [M, 3C] fp16
__device__ __half g_y[(size_t)MROWS * CC];     // [M, C]  fp16
__device__ __half g_xh[(size_t)MROWS * CC];    // x fp16 [M, C]
__device__ __half g_wat[(size_t)C3 * CC];      // W_attn^T fp16 [3C, C]
__device__ __half g_wpt[(size_t)CC * CC];      // W_proj^T fp16 [C, C]

__device__ __forceinline__ uint32_t smem_u32(const void* p) {
    return (uint32_t)__cvta_generic_to_shared(p);
}
__device__ __forceinline__ void cpasync16(uint32_t dst_smem, const void* src) {
    asm volatile("cp.async.cg.shared.global [%0], [%1], 16;"
                 :: "r"(dst_smem), "l"(src));
}
__device__ __forceinline__ void ldsm4t(uint32_t& r0, uint32_t& r1,
                                       uint32_t& r2, uint32_t& r3, uint32_t addr) {
    asm volatile("ldmatrix.sync.aligned.m8n8.x4.trans.shared.b16 {%0,%1,%2,%3}, [%4];"
                 : "=r"(r0), "=r"(r1), "=r"(r2), "=r"(r3) : "r"(addr));
}
#define HMMA(d, a, b)                                                        \
    asm volatile(                                                            \
        "mma.sync.aligned.m16n8k16.row.col.f32.f16.f16.f32 "                 \
        "{%0,%1,%2,%3}, {%4,%5,%6,%7}, {%8,%9}, {%0,%1,%2,%3};"              \
        : "+f"(d[0]), "+f"(d[1]), "+f"(d[2]), "+f"(d[3])                     \
        : "r"(a[0]), "r"(a[1]), "r"(a[2]), "r"(a[3]), "r"(b[0]), "r"(b[1]))

// ========================== prep kernels ===================================
__global__ void prep_round_h(const float* __restrict__ src,
                             __half* __restrict__ dst, int n4) {
    int i = blockIdx.x * blockDim.x + threadIdx.x;
    if (i < n4) {
        float4 v = reinterpret_cast<const float4*>(src)[i];
        __half2* d = reinterpret_cast<__half2*>(dst) + 2 * i;
        d[0] = __floats2half2_rn(v.x, v.y);
        d[1] = __floats2half2_rn(v.z, v.w);
    }
}

// W[K,N] fp32 -> Wt[N,K] fp16
__global__ void prep_transpose_h(const float* __restrict__ W,
                                 __half* __restrict__ Wt, int Kn, int Nn) {
    __shared__ float t[32][33];
    int n0 = blockIdx.x * 32, k0 = blockIdx.y * 32;
    int tx = threadIdx.x, ty = threadIdx.y;
    #pragma unroll
    for (int j = 0; j < 4; j++)
        t[ty + j * 8][tx] = W[(size_t)(k0 + ty + j * 8) * Nn + n0 + tx];
    __syncthreads();
    #pragma unroll
    for (int j = 0; j < 4; j++)
        Wt[(size_t)(n0 + ty + j * 8) * Kn + k0 + tx] =
            __float2half(t[tx][ty + j * 8]);
}

// ---------------------------------------------------------------------------
// FP16 tensor-core GEMM: C[M,N] = A[M,K] @ Bt[N,K]^T + bias[N]
// A, Bt fp16 K-major. block 256 (8 warps 2x4), tile 128x128, BK=64,
// warp tile 64x32, m16n8k16, cp.async double buffered.
// ---------------------------------------------------------------------------
#define HSTR 72                      // halfs per smem row (144B)
#define HA_HALFS (128 * HSTR)        // 9216
#define HSTAGE_BYTES (2 * HA_HALFS * 2)   // A + B per stage = 36864
#define HGEMM_SMEM_BYTES (2 * HSTAGE_BYTES)

__global__ __launch_bounds__(256, 2) void hgemm(
    const __half* __restrict__ A, const __half* __restrict__ Bt,
    const float* __restrict__ bias, void* __restrict__ Cm,
    int Mn, int Nn, int Kn, int half_out)
{
    extern __shared__ __half smh[];

    const int tid  = threadIdx.x;
    const int lane = tid & 31;
    const int warp = tid >> 5;
    const int wr   = warp & 1;
    const int wc   = warp >> 1;
    const int row0 = blockIdx.y * 128;
    const int col0 = blockIdx.x * 128;
    const int lr = lane >> 2;
    const int lc = lane & 3;

    const uint32_t smbase = smem_u32(smh);

    // 4 chunks of 16B (8 halfs) each for A and B per thread
    int rr[4], k8[4];
    #pragma unroll
    for (int i = 0; i < 4; i++) {
        int f = tid + i * 256;       // 0..1023
        rr[i] = f >> 3;              // 0..127
        k8[i] = (f & 7) << 3;        // 0,8,..,56
    }

    auto issue_stage = [&](int st, int k0) {
        uint32_t abase = smbase + st * HSTAGE_BYTES;
        uint32_t bbase = abase + HA_HALFS * 2;
        #pragma unroll
        for (int i = 0; i < 4; i++)
            cpasync16(abase + rr[i] * 144 + k8[i] * 2,
                      &A[(size_t)(row0 + rr[i]) * Kn + k0 + k8[i]]);
        #pragma unroll
        for (int i = 0; i < 4; i++)
            cpasync16(bbase + rr[i] * 144 + k8[i] * 2,
                      &Bt[(size_t)(col0 + rr[i]) * Kn + k0 + k8[i]]);
        asm volatile("cp.async.commit_group;");
    };

    float acc[4][4][4];
    #pragma unroll
    for (int i = 0; i < 4; i++)
        #pragma unroll
        for (int j = 0; j < 4; j++)
            #pragma unroll
            for (int k = 0; k < 4; k++) acc[i][j][k] = 0.0f;

    const int niter = Kn / 64;
    issue_stage(0, 0);

    for (int it = 0; it < niter; it++) {
        if (it + 1 < niter) {
            issue_stage((it + 1) & 1, (it + 1) * 64);
            asm volatile("cp.async.wait_group 1;");
        } else {
            asm volatile("cp.async.wait_group 0;");
        }
        __syncthreads();

        const __half* As = smh + (it & 1) * (HSTAGE_BYTES / 2);
        const __half* Bs = As + HA_HALFS;

        #pragma unroll
        for (int ks = 0; ks < 4; ks++) {
            const int kk = ks * 16;
            uint32_t a[4][4], b[4][2];
            #pragma unroll
            for (int mt = 0; mt < 4; mt++) {
                int m = wr * 64 + mt * 16 + lr;
                int k = kk + 2 * lc;
                a[mt][0] = *reinterpret_cast<const uint32_t*>(&As[m * HSTR + k]);
                a[mt][1] = *reinterpret_cast<const uint32_t*>(&As[(m + 8) * HSTR + k]);
                a[mt][2] = *reinterpret_cast<const uint32_t*>(&As[m * HSTR + k + 8]);
                a[mt][3] = *reinterpret_cast<const uint32_t*>(&As[(m + 8) * HSTR + k + 8]);
            }
            #pragma unroll
            for (int nt = 0; nt < 4; nt++) {
                int n = wc * 32 + nt * 8 + lr;
                int k = kk + 2 * lc;
                b[nt][0] = *reinterpret_cast<const uint32_t*>(&Bs[n * HSTR + k]);
                b[nt][1] = *reinterpret_cast<const uint32_t*>(&Bs[n * HSTR + k + 8]);
            }
            #pragma unroll
            for (int mt = 0; mt < 4; mt++)
                #pragma unroll
                for (int nt = 0; nt < 4; nt++)
                    HMMA(acc[mt][nt], a[mt], b[nt]);
        }
        __syncthreads();
    }

    #pragma unroll
    for (int mt = 0; mt < 4; mt++) {
        int r = row0 + wr * 64 + mt * 16 + lr;
        #pragma unroll
        for (int nt = 0; nt < 4; nt++) {
            int c = col0 + wc * 32 + nt * 8 + 2 * lc;
            float b0 = __ldg(&bias[c]);
            float b1 = __ldg(&bias[c + 1]);
            float v00 = acc[mt][nt][0] + b0, v01 = acc[mt][nt][1] + b1;
            float v10 = acc[mt][nt][2] + b0, v11 = acc[mt][nt][3] + b1;
            if (half_out) {
                __half* C = (__half*)Cm;
                *reinterpret_cast<__half2*>(&C[(size_t)r * Nn + c]) =
                    __floats2half2_rn(v00, v01);
                *reinterpret_cast<__half2*>(&C[(size_t)(r + 8) * Nn + c]) =
                    __floats2half2_rn(v10, v11);
            } else {
                float* C = (float*)Cm;
                *reinterpret_cast<float2*>(&C[(size_t)r * Nn + c]) =
                    make_float2(v00, v01);
                *reinterpret_cast<float2*>(&C[(size_t)(r + 8) * Nn + c]) =
                    make_float2(v10, v11);
            }
        }
    }
}

// ---------------------------------------------------------------------------
// Flash attention (causal), fp16 m16n8k16. Br=128 (8 warps x m16), Bc=64, D=64.
// smem (halfs): Qs[128][72], Ks[64][72], Vs[64][72], Ps[128][72]
// ---------------------------------------------------------------------------
#define OFF_Q  0
#define OFF_K  (128 * HSTR)
#define OFF_V  (OFF_K + 64 * HSTR)
#define OFF_P  (OFF_V + 64 * HSTR)
#define FA_SMEM_HALFS (OFF_P + 128 * HSTR)
#define FA_SMEM_BYTES (FA_SMEM_HALFS * 2)

__global__ __launch_bounds__(256, 2) void flash_h(
    const __half* __restrict__ qkv, __half* __restrict__ y)
{
    extern __shared__ __half smf[];
    __half* Qs = smf + OFF_Q;
    __half* Ks = smf + OFF_K;
    __half* Vs = smf + OFF_V;
    __half* Ps = smf + OFF_P;

    const int tid  = threadIdx.x;
    const int lane = tid & 31;
    const int w    = tid >> 5;
    const int lr   = lane >> 2;
    const int lc   = lane & 3;
    const int bx   = blockIdx.x;
    const int h    = blockIdx.y;
    const int b    = blockIdx.z;
    const int q0   = bx * 128;

    // Q tile [128 x 64] * 0.125 (exact in fp16)
    const __half2 qscale = __float2half2_rn(0.125f);
    const size_t baseQ = (size_t)(b * TT + q0) * C3 + h * DH;
    #pragma unroll
    for (int i = 0; i < 4; i++) {
        int f  = tid + i * 256;       // 0..1023 chunks
        int r  = f >> 3;              // 0..127
        int d8 = (f & 7) << 3;        // 0..56
        uint4 v = *reinterpret_cast<const uint4*>(&qkv[baseQ + (size_t)r * C3 + d8]);
        __half2* hv = reinterpret_cast<__half2*>(&v);
        hv[0] = __hmul2(hv[0], qscale);
        hv[1] = __hmul2(hv[1], qscale);
        hv[2] = __hmul2(hv[2], qscale);
        hv[3] = __hmul2(hv[3], qscale);
        *reinterpret_cast<uint4*>(&Qs[r * HSTR + d8]) = v;
    }

    float o[8][4];
    #pragma unroll
    for (int t = 0; t < 8; t++)
        #pragma unroll
        for (int j = 0; j < 4; j++) o[t][j] = 0.0f;
    float m0 = -1e30f, m1 = -1e30f, l0 = 0.0f, l1 = 0.0f;

    const int rmin = q0 + w * 16;
    const size_t baseKV = (size_t)(b * TT) * C3 + h * DH;
    const int nkt = 2 * bx + 2;

    for (int kt = 0; kt < nkt; kt++) {
        const int k0 = kt * 64;
        __syncthreads();
        #pragma unroll
        for (int i = 0; i < 2; i++) {
            int f  = tid + i * 256;      // 0..511
            int r  = f >> 3;             // 0..63
            int d8 = (f & 7) << 3;
            *reinterpret_cast<uint4*>(&Ks[r * HSTR + d8]) =
                *reinterpret_cast<const uint4*>(
                    &qkv[baseKV + (size_t)(k0 + r) * C3 + CC + d8]);
            *reinterpret_cast<uint4*>(&Vs[r * HSTR + d8]) =
                *reinterpret_cast<const uint4*>(
                    &qkv[baseKV + (size_t)(k0 + r) * C3 + 2 * CC + d8]);
        }
        __syncthreads();

        if (k0 > rmin + 15) continue;

        // ---- S = Q @ K^T : 8 n-tiles x 4 k16 steps ----
        float s[8][4];
        #pragma unroll
        for (int t = 0; t < 8; t++)
            #pragma unroll
            for (int j = 0; j < 4; j++) s[t][j] = 0.0f;

        #pragma unroll
        for (int ks = 0; ks < 4; ks++) {
            const int kk = ks * 16;
            uint32_t a[4];
            int m = w * 16 + lr;
            int k = kk + 2 * lc;
            a[0] = *reinterpret_cast<const uint32_t*>(&Qs[m * HSTR + k]);
            a[1] = *reinterpret_cast<const uint32_t*>(&Qs[(m + 8) * HSTR + k]);
            a[2] = *reinterpret_cast<const uint32_t*>(&Qs[m * HSTR + k + 8]);
            a[3] = *reinterpret_cast<const uint32_t*>(&Qs[(m + 8) * HSTR + k + 8]);
            #pragma unroll
            for (int nt = 0; nt < 8; nt++) {
                uint32_t bfr[2];
                int n = nt * 8 + lr;
                bfr[0] = *reinterpret_cast<const uint32_t*>(&Ks[n * HSTR + k]);
                bfr[1] = *reinterpret_cast<const uint32_t*>(&Ks[n * HSTR + k + 8]);
                HMMA(s[nt], a, bfr);
            }
        }

        if (k0 + 63 > rmin) {
            #pragma unroll
            for (int t = 0; t < 8; t++) {
                int c = k0 + t * 8 + 2 * lc;
                if (c > rmin + lr)          s[t][0] = -1e30f;
                if (c + 1 > rmin + lr)      s[t][1] = -1e30f;
                if (c > rmin + lr + 8)      s[t][2] = -1e30f;
                if (c + 1 > rmin + lr + 8)  s[t][3] = -1e30f;
            }
        }

        float mx0 = -1e30f, mx1 = -1e30f;
        #pragma unroll
        for (int t = 0; t < 8; t++) {
            mx0 = fmaxf(mx0, fmaxf(s[t][0], s[t][1]));
            mx1 = fmaxf(mx1, fmaxf(s[t][2], s[t][3]));
        }
        mx0 = fmaxf(mx0, __shfl_xor_sync(0xffffffffu, mx0, 1));
        mx0 = fmaxf(mx0, __shfl_xor_sync(0xffffffffu, mx0, 2));
        mx1 = fmaxf(mx1, __shfl_xor_sync(0xffffffffu, mx1, 1));
        mx1 = fmaxf(mx1, __shfl_xor_sync(0xffffffffu, mx1, 2));

        float mn0 = fmaxf(m0, mx0), mn1 = fmaxf(m1, mx1);
        float c0 = __expf(m0 - mn0), c1 = __expf(m1 - mn1);
        m0 = mn0; m1 = mn1;

        float rs0 = 0.0f, rs1 = 0.0f;
        #pragma unroll
        for (int t = 0; t < 8; t++) {
            float p00 = __expf(s[t][0] - m0);
            float p01 = __expf(s[t][1] - m0);
            float p10 = __expf(s[t][2] - m1);
            float p11 = __expf(s[t][3] - m1);
            rs0 += p00 + p01;
            rs1 += p10 + p11;
            *reinterpret_cast<__half2*>(&Ps[(w * 16 + lr) * HSTR + t * 8 + 2 * lc]) =
                __floats2half2_rn(p00, p01);
            *reinterpret_cast<__half2*>(&Ps[(w * 16 + lr + 8) * HSTR + t * 8 + 2 * lc]) =
                __floats2half2_rn(p10, p11);
            o[t][0] *= c0; o[t][1] *= c0;
            o[t][2] *= c1; o[t][3] *= c1;
        }
        rs0 += __shfl_xor_sync(0xffffffffu, rs0, 1);
        rs0 += __shfl_xor_sync(0xffffffffu, rs0, 2);
        rs1 += __shfl_xor_sync(0xffffffffu, rs1, 1);
        rs1 += __shfl_xor_sync(0xffffffffu, rs1, 2);
        l0 = l0 * c0 + rs0;
        l1 = l1 * c1 + rs1;

        __syncwarp();

        // ---- O += P @ V : 4 k16 steps, V via ldmatrix.x4.trans ----
        #pragma unroll
        for (int ks = 0; ks < 4; ks++) {
            const int kk = ks * 16;
            uint32_t a[4];
            int m = w * 16 + lr;
            int k = kk + 2 * lc;
            a[0] = *reinterpret_cast<const uint32_t*>(&Ps[m * HSTR + k]);
            a[1] = *reinterpret_cast<const uint32_t*>(&Ps[(m + 8) * HSTR + k]);
            a[2] = *reinterpret_cast<const uint32_t*>(&Ps[m * HSTR + k + 8]);
            a[3] = *reinterpret_cast<const uint32_t*>(&Ps[(m + 8) * HSTR + k + 8]);
            #pragma unroll
            for (int g = 0; g < 4; g++) {
                int n0 = g * 16;
                uint32_t vaddr = smem_u32(
                    &Vs[(kk + (lane & 15)) * HSTR + n0 + ((lane >> 4) << 3)]);
                uint32_t b0, b1, b2, b3;
                ldsm4t(b0, b1, b2, b3, vaddr);
                uint32_t bf0[2] = {b0, b1};
                uint32_t bf1[2] = {b2, b3};
                HMMA(o[2 * g],     a, bf0);
                HMMA(o[2 * g + 1], a, bf1);
            }
        }
    }

    float inv0 = 1.0f / l0, inv1 = 1.0f / l1;
    const size_t baseY = (size_t)(b * TT + q0 + w * 16) * CC + h * DH;
    #pragma unroll
    for (int t = 0; t < 8; t++) {
        int c = t * 8 + 2 * lc;
        *reinterpret_cast<__half2*>(&y[baseY + (size_t)lr * CC + c]) =
            __floats2half2_rn(o[t][0] * inv0, o[t][1] * inv0);
        *reinterpret_cast<__half2*>(&y[baseY + (size_t)(lr + 8) * CC + c]) =
            __floats2half2_rn(o[t][2] * inv1, o[t][3] * inv1);
    }
}

// ---------------------------------------------------------------------------
extern "C" void kernel_launch(void* const* d_in, const int* in_sizes, int n_in,
                              void* d_out, int out_size)
{
    const float* x      = (const float*)d_in[0];
    const float* W_attn = (const float*)d_in[1];
    const float* b_attn = (const float*)d_in[2];
    const float* W_proj = (const float*)d_in[3];
    const float* b_proj = (const float*)d_in[4];
    float* out = (float*)d_out;

    __half *qkv_ptr, *y_ptr, *xh_ptr, *wat_ptr, *wpt_ptr;
    cudaGetSymbolAddress((void**)&qkv_ptr, g_qkv);
    cudaGetSymbolAddress((void**)&y_ptr, g_y);
    cudaGetSymbolAddress((void**)&xh_ptr, g_xh);
    cudaGetSymbolAddress((void**)&wat_ptr, g_wat);
    cudaGetSymbolAddress((void**)&wpt_ptr, g_wpt);

    static bool attr_set = false;
    if (!attr_set) {
        cudaFuncSetAttribute(flash_h,
                             cudaFuncAttributeMaxDynamicSharedMemorySize,
                             FA_SMEM_BYTES);
        cudaFuncSetAttribute(hgemm,
                             cudaFuncAttributeMaxDynamicSharedMemorySize,
                             HGEMM_SMEM_BYTES);
        attr_set = true;
    }

    // prep: fp16 x, fp16 transposed weights
    prep_round_h<<<(MROWS * CC / 4 + 255) / 256, 256>>>(x, xh_ptr, MROWS * CC / 4);
    prep_transpose_h<<<dim3(C3 / 32, CC / 32), dim3(32, 8)>>>(W_attn, wat_ptr, CC, C3);
    prep_transpose_h<<<dim3(CC / 32, CC / 32), dim3(32, 8)>>>(W_proj, wpt_ptr, CC, CC);

    // 1) qkv = x @ W_attn + b_attn  (fp16 out)
    hgemm<<<dim3(C3 / 128, MROWS / 128), 256, HGEMM_SMEM_BYTES>>>(
        xh_ptr, wat_ptr, b_attn, qkv_ptr, MROWS, C3, CC, 1);

    // 2) causal flash attention -> g_y (fp16)
    flash_h<<<dim3(TT / 128, HH, BB), 256, FA_SMEM_BYTES>>>(qkv_ptr, y_ptr);

    // 3) out = y @ W_proj + b_proj  (fp32 out)
    hgemm<<<dim3(CC / 128, MROWS / 128), 256, HGEMM_SMEM_BYTES>>>(
        y_ptr, wpt_ptr, b_proj, out, MROWS, CC, CC, 0);
}

// round 9
// speedup vs baseline: 8.3687x; 1.1629x over previous
#include <cuda_runtime.h>
#include <cuda_fp16.h>
#include <math.h>
#include <stdint.h>

#define BB 4
#define TT 2048
#define CC 1024
#define HH 16
#define DH 64
#define MROWS (BB*TT)
#define C3   (3*CC)

// scratch (no cudaMalloc allowed)
__device__ __half g_qkv[(size_t)MROWS * C3];   // [M, 3C] fp16
__device__ __half g_y[(size_t)MROWS * CC];     // [M, C]  fp16
__device__ __half g_xh[(size_t)MROWS * CC];    // x fp16 [M, C]
__device__ __half g_wat[(size_t)C3 * CC];      // W_attn^T fp16 [3C, C]
__device__ __half g_wpt[(size_t)CC * CC];      // W_proj^T fp16 [C, C]

__device__ __forceinline__ uint32_t smem_u32(const void* p) {
    return (uint32_t)__cvta_generic_to_shared(p);
}
__device__ __forceinline__ void cpasync16(uint32_t dst_smem, const void* src) {
    asm volatile("cp.async.cg.shared.global [%0], [%1], 16;"
                 :: "r"(dst_smem), "l"(src));
}
__device__ __forceinline__ void ldsm4(uint32_t& r0, uint32_t& r1,
                                      uint32_t& r2, uint32_t& r3, uint32_t addr) {
    asm volatile("ldmatrix.sync.aligned.m8n8.x4.shared.b16 {%0,%1,%2,%3}, [%4];"
                 : "=r"(r0), "=r"(r1), "=r"(r2), "=r"(r3) : "r"(addr));
}
__device__ __forceinline__ void ldsm4t(uint32_t& r0, uint32_t& r1,
                                       uint32_t& r2, uint32_t& r3, uint32_t addr) {
    asm volatile("ldmatrix.sync.aligned.m8n8.x4.trans.shared.b16 {%0,%1,%2,%3}, [%4];"
                 : "=r"(r0), "=r"(r1), "=r"(r2), "=r"(r3) : "r"(addr));
}
#define HMMA(d, a, b)                                                        \
    asm volatile(                                                            \
        "mma.sync.aligned.m16n8k16.row.col.f32.f16.f16.f32 "                 \
        "{%0,%1,%2,%3}, {%4,%5,%6,%7}, {%8,%9}, {%0,%1,%2,%3};"              \
        : "+f"(d[0]), "+f"(d[1]), "+f"(d[2]), "+f"(d[3])                     \
        : "r"(a[0]), "r"(a[1]), "r"(a[2]), "r"(a[3]), "r"(b[0]), "r"(b[1]))

__device__ __forceinline__ uint32_t packh2(float x, float y) {
    __half2 h = __floats2half2_rn(x, y);
    return *reinterpret_cast<uint32_t*>(&h);
}

// ========================== prep kernels ===================================
__global__ void prep_round_h(const float* __restrict__ src,
                             __half* __restrict__ dst, int n4) {
    int i = blockIdx.x * blockDim.x + threadIdx.x;
    if (i < n4) {
        float4 v = reinterpret_cast<const float4*>(src)[i];
        __half2* d = reinterpret_cast<__half2*>(dst) + 2 * i;
        d[0] = __floats2half2_rn(v.x, v.y);
        d[1] = __floats2half2_rn(v.z, v.w);
    }
}

__global__ void prep_transpose_h(const float* __restrict__ W,
                                 __half* __restrict__ Wt, int Kn, int Nn) {
    __shared__ float t[32][33];
    int n0 = blockIdx.x * 32, k0 = blockIdx.y * 32;
    int tx = threadIdx.x, ty = threadIdx.y;
    #pragma unroll
    for (int j = 0; j < 4; j++)
        t[ty + j * 8][tx] = W[(size_t)(k0 + ty + j * 8) * Nn + n0 + tx];
    __syncthreads();
    #pragma unroll
    for (int j = 0; j < 4; j++)
        Wt[(size_t)(n0 + ty + j * 8) * Kn + k0 + tx] =
            __float2half(t[tx][ty + j * 8]);
}

// ---------------------------------------------------------------------------
// FP16 GEMM: C[M,N] = A[M,K] @ Bt[N,K]^T + bias[N]
// block 256 (8 warps 2x4), tile 128x128, BK=64, warp tile 64x32.
// 3-stage cp.async ring, ldmatrix fragment loads, 1 syncthreads/iter.
// ---------------------------------------------------------------------------
#define HSTR 72                           // halfs per smem row (144 B)
#define HA_HALFS (128 * HSTR)             // 9216 halfs per operand tile
#define HSTAGE_BYTES (2 * HA_HALFS * 2)   // A + B = 36864 B
#define HGEMM_SMEM_BYTES (3 * HSTAGE_BYTES)

__global__ __launch_bounds__(256, 2) void hgemm(
    const __half* __restrict__ A, const __half* __restrict__ Bt,
    const float* __restrict__ bias, void* __restrict__ Cm,
    int Mn, int Nn, int Kn, int half_out)
{
    extern __shared__ __half smh[];

    const int tid  = threadIdx.x;
    const int lane = tid & 31;
    const int warp = tid >> 5;
    const int wr   = warp & 1;
    const int wc   = warp >> 1;
    const int row0 = blockIdx.y * 128;
    const int col0 = blockIdx.x * 128;
    const int lr = lane >> 2;
    const int lc = lane & 3;

    const uint32_t smbase = smem_u32(smh);

    // ldmatrix lane offsets (halfs)
    const int lmr = lane & 7, lmj = lane >> 3;
    const int a_loff = ((lmj & 1) * 8 + lmr) * HSTR + (lmj >> 1) * 8;
    const int b_loff = ((lmj >> 1) * 8 + lmr) * HSTR + (lmj & 1) * 8;

    int rr[4], k8[4];
    #pragma unroll
    for (int i = 0; i < 4; i++) {
        int f = tid + i * 256;
        rr[i] = f >> 3;
        k8[i] = (f & 7) << 3;
    }

    auto issue_stage = [&](int st, int k0) {
        uint32_t abase = smbase + st * HSTAGE_BYTES;
        uint32_t bbase = abase + HA_HALFS * 2;
        #pragma unroll
        for (int i = 0; i < 4; i++)
            cpasync16(abase + rr[i] * 144 + k8[i] * 2,
                      &A[(size_t)(row0 + rr[i]) * Kn + k0 + k8[i]]);
        #pragma unroll
        for (int i = 0; i < 4; i++)
            cpasync16(bbase + rr[i] * 144 + k8[i] * 2,
                      &Bt[(size_t)(col0 + rr[i]) * Kn + k0 + k8[i]]);
        asm volatile("cp.async.commit_group;");
    };

    float acc[4][4][4];
    #pragma unroll
    for (int i = 0; i < 4; i++)
        #pragma unroll
        for (int j = 0; j < 4; j++)
            #pragma unroll
            for (int k = 0; k < 4; k++) acc[i][j][k] = 0.0f;

    const int niter = Kn / 64;
    issue_stage(0, 0);
    if (niter > 1) issue_stage(1, 64);

    for (int it = 0; it < niter; it++) {
        if (it + 1 < niter) asm volatile("cp.async.wait_group 1;");
        else                asm volatile("cp.async.wait_group 0;");
        __syncthreads();

        const int stage = it % 3;
        const uint32_t aBase = smbase + stage * HSTAGE_BYTES;
        const uint32_t bBase = aBase + HA_HALFS * 2;

        #pragma unroll
        for (int ks = 0; ks < 4; ks++) {
            const int kk = ks * 16;
            uint32_t a[4][4], b[4][2];
            #pragma unroll
            for (int mt = 0; mt < 4; mt++)
                ldsm4(a[mt][0], a[mt][1], a[mt][2], a[mt][3],
                      aBase + (((wr * 64 + mt * 16) * HSTR + kk) + a_loff) * 2);
            #pragma unroll
            for (int p = 0; p < 2; p++) {
                uint32_t r0, r1, r2, r3;
                ldsm4(r0, r1, r2, r3,
                      bBase + (((wc * 32 + p * 16) * HSTR + kk) + b_loff) * 2);
                b[2 * p][0] = r0; b[2 * p][1] = r1;
                b[2 * p + 1][0] = r2; b[2 * p + 1][1] = r3;
            }
            #pragma unroll
            for (int mt = 0; mt < 4; mt++)
                #pragma unroll
                for (int nt = 0; nt < 4; nt++)
                    HMMA(acc[mt][nt], a[mt], b[nt]);
        }

        if (it + 2 < niter) issue_stage((it + 2) % 3, (it + 2) * 64);
    }

    #pragma unroll
    for (int mt = 0; mt < 4; mt++) {
        int r = row0 + wr * 64 + mt * 16 + lr;
        #pragma unroll
        for (int nt = 0; nt < 4; nt++) {
            int c = col0 + wc * 32 + nt * 8 + 2 * lc;
            float b0 = __ldg(&bias[c]);
            float b1 = __ldg(&bias[c + 1]);
            float v00 = acc[mt][nt][0] + b0, v01 = acc[mt][nt][1] + b1;
            float v10 = acc[mt][nt][2] + b0, v11 = acc[mt][nt][3] + b1;
            if (half_out) {
                __half* C = (__half*)Cm;
                *reinterpret_cast<__half2*>(&C[(size_t)r * Nn + c]) =
                    __floats2half2_rn(v00, v01);
                *reinterpret_cast<__half2*>(&C[(size_t)(r + 8) * Nn + c]) =
                    __floats2half2_rn(v10, v11);
            } else {
                float* C = (float*)Cm;
                *reinterpret_cast<float2*>(&C[(size_t)r * Nn + c]) =
                    make_float2(v00, v01);
                *reinterpret_cast<float2*>(&C[(size_t)(r + 8) * Nn + c]) =
                    make_float2(v10, v11);
            }
        }
    }
}

// ---------------------------------------------------------------------------
// Flash attention (causal), fp16 m16n8k16. Br=128 (8 warps), Bc=64, D=64.
// S C-frag reused directly as P A-frag (no P smem round-trip).
// smem (halfs): Qs[128][72], Ks[64][72], Vs[64][72]
// ---------------------------------------------------------------------------
#define OFF_Q  0
#define OFF_K  (128 * HSTR)
#define OFF_V  (OFF_K + 64 * HSTR)
#define FA_SMEM_HALFS (OFF_V + 64 * HSTR)
#define FA_SMEM_BYTES (FA_SMEM_HALFS * 2)

__global__ __launch_bounds__(256, 2) void flash_h(
    const __half* __restrict__ qkv, __half* __restrict__ y)
{
    extern __shared__ __half smf[];
    __half* Qs = smf + OFF_Q;
    __half* Ks = smf + OFF_K;
    __half* Vs = smf + OFF_V;

    const int tid  = threadIdx.x;
    const int lane = tid & 31;
    const int w    = tid >> 5;
    const int lr   = lane >> 2;
    const int lc   = lane & 3;
    const int bx   = blockIdx.x;
    const int h    = blockIdx.y;
    const int b    = blockIdx.z;
    const int q0   = bx * 128;

    const uint32_t qBase = smem_u32(Qs);
    const uint32_t kBase = smem_u32(Ks);

    const int lmr = lane & 7, lmj = lane >> 3;
    const int a_loff = ((lmj & 1) * 8 + lmr) * HSTR + (lmj >> 1) * 8;
    const int b_loff = ((lmj >> 1) * 8 + lmr) * HSTR + (lmj & 1) * 8;

    // Q tile [128 x 64] * 0.125 (exact in fp16)
    const __half2 qscale = __float2half2_rn(0.125f);
    const size_t baseQ = (size_t)(b * TT + q0) * C3 + h * DH;
    #pragma unroll
    for (int i = 0; i < 4; i++) {
        int f  = tid + i * 256;
        int r  = f >> 3;
        int d8 = (f & 7) << 3;
        uint4 v = *reinterpret_cast<const uint4*>(&qkv[baseQ + (size_t)r * C3 + d8]);
        __half2* hv = reinterpret_cast<__half2*>(&v);
        hv[0] = __hmul2(hv[0], qscale);
        hv[1] = __hmul2(hv[1], qscale);
        hv[2] = __hmul2(hv[2], qscale);
        hv[3] = __hmul2(hv[3], qscale);
        *reinterpret_cast<uint4*>(&Qs[r * HSTR + d8]) = v;
    }

    float o[8][4];
    #pragma unroll
    for (int t = 0; t < 8; t++)
        #pragma unroll
        for (int j = 0; j < 4; j++) o[t][j] = 0.0f;
    float m0 = -1e30f, m1 = -1e30f, l0 = 0.0f, l1 = 0.0f;

    const int rmin = q0 + w * 16;
    const size_t baseKV = (size_t)(b * TT) * C3 + h * DH;
    const int nkt = 2 * bx + 2;

    for (int kt = 0; kt < nkt; kt++) {
        const int k0 = kt * 64;
        __syncthreads();
        #pragma unroll
        for (int i = 0; i < 2; i++) {
            int f  = tid + i * 256;
            int r  = f >> 3;
            int d8 = (f & 7) << 3;
            *reinterpret_cast<uint4*>(&Ks[r * HSTR + d8]) =
                *reinterpret_cast<const uint4*>(
                    &qkv[baseKV + (size_t)(k0 + r) * C3 + CC + d8]);
            *reinterpret_cast<uint4*>(&Vs[r * HSTR + d8]) =
                *reinterpret_cast<const uint4*>(
                    &qkv[baseKV + (size_t)(k0 + r) * C3 + 2 * CC + d8]);
        }
        __syncthreads();

        if (k0 > rmin + 15) continue;

        // ---- S = Q @ K^T : ldmatrix fragments ----
        float s[8][4];
        #pragma unroll
        for (int t = 0; t < 8; t++)
            #pragma unroll
            for (int j = 0; j < 4; j++) s[t][j] = 0.0f;

        #pragma unroll
        for (int ks = 0; ks < 4; ks++) {
            const int kk = ks * 16;
            uint32_t a[4];
            ldsm4(a[0], a[1], a[2], a[3],
                  qBase + ((w * 16) * HSTR + kk + a_loff) * 2);
            #pragma unroll
            for (int p = 0; p < 4; p++) {
                uint32_t r0, r1, r2, r3;
                ldsm4(r0, r1, r2, r3,
                      kBase + ((p * 16) * HSTR + kk + b_loff) * 2);
                uint32_t bf0[2] = {r0, r1};
                uint32_t bf1[2] = {r2, r3};
                HMMA(s[2 * p],     a, bf0);
                HMMA(s[2 * p + 1], a, bf1);
            }
        }

        if (k0 + 63 > rmin) {
            #pragma unroll
            for (int t = 0; t < 8; t++) {
                int c = k0 + t * 8 + 2 * lc;
                if (c > rmin + lr)          s[t][0] = -1e30f;
                if (c + 1 > rmin + lr)      s[t][1] = -1e30f;
                if (c > rmin + lr + 8)      s[t][2] = -1e30f;
                if (c + 1 > rmin + lr + 8)  s[t][3] = -1e30f;
            }
        }

        float mx0 = -1e30f, mx1 = -1e30f;
        #pragma unroll
        for (int t = 0; t < 8; t++) {
            mx0 = fmaxf(mx0, fmaxf(s[t][0], s[t][1]));
            mx1 = fmaxf(mx1, fmaxf(s[t][2], s[t][3]));
        }
        mx0 = fmaxf(mx0, __shfl_xor_sync(0xffffffffu, mx0, 1));
        mx0 = fmaxf(mx0, __shfl_xor_sync(0xffffffffu, mx0, 2));
        mx1 = fmaxf(mx1, __shfl_xor_sync(0xffffffffu, mx1, 1));
        mx1 = fmaxf(mx1, __shfl_xor_sync(0xffffffffu, mx1, 2));

        float mn0 = fmaxf(m0, mx0), mn1 = fmaxf(m1, mx1);
        float c0 = __expf(m0 - mn0), c1 = __expf(m1 - mn1);
        m0 = mn0; m1 = mn1;

        float rs0 = 0.0f, rs1 = 0.0f;
        #pragma unroll
        for (int t = 0; t < 8; t++) {
            s[t][0] = __expf(s[t][0] - m0);
            s[t][1] = __expf(s[t][1] - m0);
            s[t][2] = __expf(s[t][2] - m1);
            s[t][3] = __expf(s[t][3] - m1);
            rs0 += s[t][0] + s[t][1];
            rs1 += s[t][2] + s[t][3];
            o[t][0] *= c0; o[t][1] *= c0;
            o[t][2] *= c1; o[t][3] *= c1;
        }
        rs0 += __shfl_xor_sync(0xffffffffu, rs0, 1);
        rs0 += __shfl_xor_sync(0xffffffffu, rs0, 2);
        rs1 += __shfl_xor_sync(0xffffffffu, rs1, 1);
        rs1 += __shfl_xor_sync(0xffffffffu, rs1, 2);
        l0 = l0 * c0 + rs0;
        l1 = l1 * c1 + rs1;

        // ---- O += P @ V : P A-frags packed directly from S C-frags ----
        #pragma unroll
        for (int ks = 0; ks < 4; ks++) {
            const int kk = ks * 16;
            uint32_t a[4];
            a[0] = packh2(s[2 * ks][0], s[2 * ks][1]);
            a[1] = packh2(s[2 * ks][2], s[2 * ks][3]);
            a[2] = packh2(s[2 * ks + 1][0], s[2 * ks + 1][1]);
            a[3] = packh2(s[2 * ks + 1][2], s[2 * ks + 1][3]);
            #pragma unroll
            for (int g = 0; g < 4; g++) {
                int n0 = g * 16;
                uint32_t vaddr = smem_u32(
                    &Vs[(kk + (lane & 15)) * HSTR + n0 + ((lane >> 4) << 3)]);
                uint32_t b0, b1, b2, b3;
                ldsm4t(b0, b1, b2, b3, vaddr);
                uint32_t bf0[2] = {b0, b1};
                uint32_t bf1[2] = {b2, b3};
                HMMA(o[2 * g],     a, bf0);
                HMMA(o[2 * g + 1], a, bf1);
            }
        }
    }

    float inv0 = 1.0f / l0, inv1 = 1.0f / l1;
    const size_t baseY = (size_t)(b * TT + q0 + w * 16) * CC + h * DH;
    #pragma unroll
    for (int t = 0; t < 8; t++) {
        int c = t * 8 + 2 * lc;
        *reinterpret_cast<__half2*>(&y[baseY + (size_t)lr * CC + c]) =
            __floats2half2_rn(o[t][0] * inv0, o[t][1] * inv0);
        *reinterpret_cast<__half2*>(&y[baseY + (size_t)(lr + 8) * CC + c]) =
            __floats2half2_rn(o[t][2] * inv1, o[t][3] * inv1);
    }
}

// ---------------------------------------------------------------------------
extern "C" void kernel_launch(void* const* d_in, const int* in_sizes, int n_in,
                              void* d_out, int out_size)
{
    const float* x      = (const float*)d_in[0];
    const float* W_attn = (const float*)d_in[1];
    const float* b_attn = (const float*)d_in[2];
    const float* W_proj = (const float*)d_in[3];
    const float* b_proj = (const float*)d_in[4];
    float* out = (float*)d_out;

    __half *qkv_ptr, *y_ptr, *xh_ptr, *wat_ptr, *wpt_ptr;
    cudaGetSymbolAddress((void**)&qkv_ptr, g_qkv);
    cudaGetSymbolAddress((void**)&y_ptr, g_y);
    cudaGetSymbolAddress((void**)&xh_ptr, g_xh);
    cudaGetSymbolAddress((void**)&wat_ptr, g_wat);
    cudaGetSymbolAddress((void**)&wpt_ptr, g_wpt);

    static bool attr_set = false;
    if (!attr_set) {
        cudaFuncSetAttribute(flash_h,
                             cudaFuncAttributeMaxDynamicSharedMemorySize,
                             FA_SMEM_BYTES);
        cudaFuncSetAttribute(hgemm,
                             cudaFuncAttributeMaxDynamicSharedMemorySize,
                             HGEMM_SMEM_BYTES);
        attr_set = true;
    }

    prep_round_h<<<(MROWS * CC / 4 + 255) / 256, 256>>>(x, xh_ptr, MROWS * CC / 4);
    prep_transpose_h<<<dim3(C3 / 32, CC / 32), dim3(32, 8)>>>(W_attn, wat_ptr, CC, C3);
    prep_transpose_h<<<dim3(CC / 32, CC / 32), dim3(32, 8)>>>(W_proj, wpt_ptr, CC, CC);

    hgemm<<<dim3(C3 / 128, MROWS / 128), 256, HGEMM_SMEM_BYTES>>>(
        xh_ptr, wat_ptr, b_attn, qkv_ptr, MROWS, C3, CC, 1);

    flash_h<<<dim3(TT / 128, HH, BB), 256, FA_SMEM_BYTES>>>(qkv_ptr, y_ptr);

    hgemm<<<dim3(CC / 128, MROWS / 128), 256, HGEMM_SMEM_BYTES>>>(
        y_ptr, wpt_ptr, b_proj, out, MROWS, CC, CC, 0);
}